// round 8
// baseline (speedup 1.0000x reference)
#include <cuda_runtime.h>
#include <math.h>
#include <stdint.h>

#define Bn 4
#define Tn 2048
#define En 1024
#define Hn 2048
#define BT (Bn*Tn)
#define ATTN_SCALE 0.022097086912079612f

// ---------------- scratch (static device memory; no cudaMalloc) -------------
__device__ float g_q  [(size_t)BT * Hn];   // q (tf32-rounded)
__device__ float g_vt [(size_t)Hn * BT];   // v^T as [H, B*T]
__device__ float g_e  [(size_t)BT * Tn];   // exp'd masked scores
__device__ float g_xr [(size_t)BT * En];   // x rounded to tf32
__device__ float g_wtq[(size_t)Hn * En];   // Wq^T rounded
__device__ float g_wtv[(size_t)Hn * En];   // Wv^T rounded
__device__ float g_d  [BT];                // softmax denominators

// ---------------- helpers ----------------------------------------------------
__device__ __forceinline__ float tf32r(float x) {
    uint32_t u;
    asm("cvt.rna.tf32.f32 %0, %1;" : "=r"(u) : "f"(x));
    return __uint_as_float(u);
}
__device__ __forceinline__ uint32_t smem_u32(const void* p) {
    uint32_t a;
    asm("{ .reg .u64 t; cvta.to.shared.u64 t, %1; cvt.u32.u64 %0, t; }" : "=r"(a) : "l"(p));
    return a;
}
__device__ __forceinline__ void cp16(uint32_t s, const void* g) {
    asm volatile("cp.async.ca.shared.global [%0], [%1], 16;" :: "r"(s), "l"(g));
}
#define CP_COMMIT() asm volatile("cp.async.commit_group;" ::: "memory")
#define CP_WAIT(n)  asm volatile("cp.async.wait_group %0;" :: "n"(n) : "memory")

__device__ __forceinline__ void mma8(float* d, const uint32_t* a, const uint32_t* b) {
    asm volatile(
        "mma.sync.aligned.m16n8k8.row.col.f32.tf32.tf32.f32 "
        "{%0,%1,%2,%3}, {%4,%5,%6,%7}, {%8,%9}, {%0,%1,%2,%3};"
        : "+f"(d[0]), "+f"(d[1]), "+f"(d[2]), "+f"(d[3])
        : "r"(a[0]), "r"(a[1]), "r"(a[2]), "r"(a[3]), "r"(b[0]), "r"(b[1]));
}

// ---------------- tensor-core GEMM (NT: A[M,K] x B[N,K] -> C[M,N]) -----------
// MODE 0: C = tf32(acc + bias[col])      (q projection)
// MODE 1: C = tf32(acc + bias[row])      (v^T projection)
// MODE 2: C = tf32(r>=c ? exp(acc*s):1)  (scores -> E)
// MODE 3: C = acc                        (final output)
#define LDS_S 36                    // padded smem row stride (floats)
#define STAGE_F (128 * LDS_S)       // 4608 floats per tile stage
#define SMEM_BYTES (4 * STAGE_F * 4)  // A0,A1,B0,B1 = 73728 B

template <int MODE>
__global__ void __launch_bounds__(256, 2) mm_mma(
    const float* __restrict__ A, const float* __restrict__ B,
    const float* __restrict__ bias, float* __restrict__ C,
    int K, int ldA, int ldB, int ldC,
    long long zA, long long zB, long long zC)
{
    extern __shared__ float sm[];
    const int z = blockIdx.z;
    A += z * zA; B += z * zB; C += z * zC;

    const int tid  = threadIdx.x;
    const int wid  = tid >> 5, lane = tid & 31;
    const int wm   = wid & 1, wn = wid >> 1;      // warp tile: 64x32
    const int grp  = lane >> 2, tig = lane & 3;
    const int brow = blockIdx.y * 128, bcol = blockIdx.x * 128;

    float* As[2] = { sm,             sm + STAGE_F };
    float* Bs[2] = { sm + 2*STAGE_F, sm + 3*STAGE_F };
    const uint32_t sA0 = smem_u32(As[0]), sB0 = smem_u32(Bs[0]);

    // tile loaders: 128 rows x 32 cols, 1024 float4, 256 threads x 4
    const int lr = tid >> 3, lc4 = (tid & 7) * 4;       // row, col within tile

    float acc[4][4][4];
#pragma unroll
    for (int i = 0; i < 4; i++)
#pragma unroll
        for (int j = 0; j < 4; j++)
#pragma unroll
            for (int k = 0; k < 4; k++) acc[i][j][k] = 0.0f;

    const int nk = K >> 5;

    // prologue: stage 0
#pragma unroll
    for (int j = 0; j < 4; j++) {
        const int r = lr + 32 * j;
        cp16(sA0 + (r * LDS_S + lc4) * 4, A + (size_t)(brow + r) * ldA + lc4);
        cp16(sB0 + (r * LDS_S + lc4) * 4, B + (size_t)(bcol + r) * ldB + lc4);
    }
    CP_COMMIT();

    for (int i = 0; i < nk; i++) {
        const int cur = i & 1;
        if (i + 1 < nk) {
            const int nxt = cur ^ 1;
            const int k0 = (i + 1) * 32;
            const uint32_t sAn = sA0 + nxt * STAGE_F * 4;
            const uint32_t sBn = sB0 + (nxt + 2) * STAGE_F * 4 - 2 * STAGE_F * 4; // = sB0 + nxt*STAGE_F*4
#pragma unroll
            for (int j = 0; j < 4; j++) {
                const int r = lr + 32 * j;
                cp16(sAn + (r * LDS_S + lc4) * 4, A + (size_t)(brow + r) * ldA + k0 + lc4);
                cp16(sBn + (r * LDS_S + lc4) * 4, B + (size_t)(bcol + r) * ldB + k0 + lc4);
            }
            CP_COMMIT();
            CP_WAIT(1);
        } else {
            CP_WAIT(0);
        }
        __syncthreads();

        const float* as = As[cur];
        const float* bs = Bs[cur];
#pragma unroll
        for (int k8 = 0; k8 < 4; k8++) {
            uint32_t afr[4][4], bfr[4][2];
#pragma unroll
            for (int mi = 0; mi < 4; mi++) {
                const float* p = as + (wm * 64 + mi * 16 + grp) * LDS_S + k8 * 8 + tig;
                afr[mi][0] = __float_as_uint(p[0]);
                afr[mi][1] = __float_as_uint(p[8 * LDS_S]);
                afr[mi][2] = __float_as_uint(p[4]);
                afr[mi][3] = __float_as_uint(p[8 * LDS_S + 4]);
            }
#pragma unroll
            for (int ni = 0; ni < 4; ni++) {
                const float* p = bs + (wn * 32 + ni * 8 + grp) * LDS_S + k8 * 8 + tig;
                bfr[ni][0] = __float_as_uint(p[0]);
                bfr[ni][1] = __float_as_uint(p[4]);
            }
#pragma unroll
            for (int mi = 0; mi < 4; mi++)
#pragma unroll
                for (int ni = 0; ni < 4; ni++)
                    mma8(acc[mi][ni], afr[mi], bfr[ni]);
        }
        __syncthreads();
    }

    // ---------------- epilogue ----------------
#pragma unroll
    for (int mi = 0; mi < 4; mi++) {
        const int r0 = brow + wm * 64 + mi * 16 + grp;   // batch-local row
#pragma unroll
        for (int half = 0; half < 2; half++) {
            const int r = r0 + half * 8;
            float rbias = 0.0f;
            if (MODE == 1) rbias = __ldg(&bias[r]);
#pragma unroll
            for (int ni = 0; ni < 4; ni++) {
                const int c = bcol + wn * 32 + ni * 8 + 2 * tig;
                float v0 = acc[mi][ni][half * 2 + 0];
                float v1 = acc[mi][ni][half * 2 + 1];
                if (MODE == 0) {
                    v0 = tf32r(v0 + __ldg(&bias[c]));
                    v1 = tf32r(v1 + __ldg(&bias[c + 1]));
                } else if (MODE == 1) {
                    v0 = tf32r(v0 + rbias);
                    v1 = tf32r(v1 + rbias);
                } else if (MODE == 2) {
                    v0 = tf32r((r >= c)     ? expf(v0 * ATTN_SCALE) : 1.0f);
                    v1 = tf32r((r >= c + 1) ? expf(v1 * ATTN_SCALE) : 1.0f);
                }
                *reinterpret_cast<float2*>(C + (size_t)r * ldC + c) = make_float2(v0, v1);
            }
        }
    }
}

// ---------------- small kernels ---------------------------------------------
__global__ void __launch_bounds__(256) transpose_round(
    const float* __restrict__ src, float* __restrict__ dst, int R, int Cc)
{
    __shared__ float t[32][33];
    const int x = blockIdx.x * 32 + threadIdx.x;
    const int y0 = blockIdx.y * 32;
#pragma unroll
    for (int j = 0; j < 32; j += 8)
        t[threadIdx.y + j][threadIdx.x] = src[(size_t)(y0 + threadIdx.y + j) * Cc + x];
    __syncthreads();
    const int xo = y0 + threadIdx.x;
    const int yo0 = blockIdx.x * 32;
#pragma unroll
    for (int j = 0; j < 32; j += 8)
        dst[(size_t)(yo0 + threadIdx.y + j) * R + xo] = tf32r(t[threadIdx.x][threadIdx.y + j]);
}

__global__ void __launch_bounds__(256) round_x(const float* __restrict__ in, float* __restrict__ o)
{
    const size_t i = (size_t)blockIdx.x * 256 + threadIdx.x;
    float4 v = reinterpret_cast<const float4*>(in)[i];
    v.x = tf32r(v.x); v.y = tf32r(v.y); v.z = tf32r(v.z); v.w = tf32r(v.w);
    reinterpret_cast<float4*>(o)[i] = v;
}

__global__ void __launch_bounds__(256) zero_d(float* __restrict__ D)
{
    D[blockIdx.x * 256 + threadIdx.x] = 0.0f;
}

// D[b*Tn + k] += sum over a 256-row chunk of E[:, k] (softmax over query axis)
__global__ void __launch_bounds__(256) colsum(const float* __restrict__ E, float* __restrict__ D)
{
    const int k = blockIdx.x * 256 + threadIdx.x;
    const int b = blockIdx.y;
    const int rc = blockIdx.z;
    const float* p = E + ((size_t)b * Tn + (size_t)rc * 256) * Tn + k;
    float s = 0.0f;
#pragma unroll 8
    for (int q = 0; q < 256; q++) s += p[(size_t)q * Tn];
    atomicAdd(&D[b * Tn + k], s);
}

// vt[h, b*T+t] /= D[b*T+t], round to tf32
__global__ void __launch_bounds__(256) vtscale(float* __restrict__ VT, const float* __restrict__ D)
{
    const size_t i4 = (size_t)blockIdx.x * 256 + threadIdx.x;
    float4 v = reinterpret_cast<float4*>(VT)[i4];
    const int col4 = (int)(i4 & (BT / 4 - 1));
    const float4 d = reinterpret_cast<const float4*>(D)[col4];
    v.x = tf32r(v.x / d.x); v.y = tf32r(v.y / d.y);
    v.z = tf32r(v.z / d.z); v.w = tf32r(v.w / d.w);
    reinterpret_cast<float4*>(VT)[i4] = v;
}

// ---------------- host -------------------------------------------------------
extern "C" void kernel_launch(void* const* d_in, const int* in_sizes, int n_in,
                              void* d_out, int out_size)
{
    (void)in_sizes; (void)n_in; (void)out_size;
    const float* x  = (const float*)d_in[0];
    const float* Wq = (const float*)d_in[1];
    const float* bq = (const float*)d_in[2];
    const float* Wv = (const float*)d_in[3];
    const float* bv = (const float*)d_in[4];
    float* out = (float*)d_out;

    float *q, *vt, *e, *xr, *wtq, *wtv, *dI;
    cudaGetSymbolAddress((void**)&q,   g_q);
    cudaGetSymbolAddress((void**)&vt,  g_vt);
    cudaGetSymbolAddress((void**)&e,   g_e);
    cudaGetSymbolAddress((void**)&xr,  g_xr);
    cudaGetSymbolAddress((void**)&wtq, g_wtq);
    cudaGetSymbolAddress((void**)&wtv, g_wtv);
    cudaGetSymbolAddress((void**)&dI,  g_d);

    cudaFuncSetAttribute(mm_mma<0>, cudaFuncAttributeMaxDynamicSharedMemorySize, SMEM_BYTES);
    cudaFuncSetAttribute(mm_mma<1>, cudaFuncAttributeMaxDynamicSharedMemorySize, SMEM_BYTES);
    cudaFuncSetAttribute(mm_mma<2>, cudaFuncAttributeMaxDynamicSharedMemorySize, SMEM_BYTES);
    cudaFuncSetAttribute(mm_mma<3>, cudaFuncAttributeMaxDynamicSharedMemorySize, SMEM_BYTES);

    // prep: transpose+round weights, round x, zero denominators
    transpose_round<<<dim3(Hn / 32, En / 32), dim3(32, 8)>>>(Wq, wtq, En, Hn);
    transpose_round<<<dim3(Hn / 32, En / 32), dim3(32, 8)>>>(Wv, wtv, En, Hn);
    round_x<<<(int)(((size_t)BT * En / 4) / 256), 256>>>(x, xr);
    zero_d<<<BT / 256, 256>>>(dI);

    // q = x @ Wq + bq                    [B*T, H]
    mm_mma<0><<<dim3(Hn / 128, BT / 128, 1), 256, SMEM_BYTES>>>(
        xr, wtq, bq, q, En, En, En, Hn, 0, 0, 0);
    // v^T = (x @ Wv + bv)^T              [H, B*T]
    mm_mma<1><<<dim3(BT / 128, Hn / 128, 1), 256, SMEM_BYTES>>>(
        wtv, xr, bv, vt, En, En, En, BT, 0, 0, 0);
    // E = exp(mask .* (q @ q^T) * s)     per batch
    mm_mma<2><<<dim3(Tn / 128, Tn / 128, Bn), 256, SMEM_BYTES>>>(
        q, q, nullptr, e, Hn, Hn, Hn, Tn,
        (long long)Tn * Hn, (long long)Tn * Hn, (long long)Tn * Tn);
    // softmax denominators + fold into v^T columns
    colsum<<<dim3(Tn / 256, Bn, Tn / 256), 256>>>(e, dI);
    vtscale<<<(int)(((size_t)Hn * BT / 4) / 256), 256>>>(vt, dI);
    // out = E @ v'                       per batch
    mm_mma<3><<<dim3(Hn / 128, Tn / 128, Bn), 256, SMEM_BYTES>>>(
        e, vt, nullptr, out, Tn, Tn, BT, Hn,
        (long long)Tn * Tn, (long long)Tn, (long long)Tn * Hn);
}

// round 9
// speedup vs baseline: 1.3284x; 1.3284x over previous
#include <cuda_runtime.h>
#include <math.h>
#include <stdint.h>

#define Bn 4
#define Tn 2048
#define En 1024
#define Hn 2048
#define BT (Bn*Tn)
#define NBK (Tn/128)               // 16 blocks along T
#define ATTN_SCALE 0.022097086912079612f

// ---------------- scratch (static device memory; no cudaMalloc) -------------
__device__ float g_q  [(size_t)BT * Hn];   // q (tf32-rounded)
__device__ float g_vt [(size_t)Hn * BT];   // v^T as [H, B*T]
__device__ float g_e  [(size_t)BT * Tn];   // exp'd masked scores (lower blocks only)
__device__ float g_xr [(size_t)BT * En];   // x rounded to tf32
__device__ float g_wtq[(size_t)Hn * En];   // Wq^T rounded
__device__ float g_wtv[(size_t)Hn * En];   // Wv^T rounded
__device__ float g_d  [BT];                // softmax denominators
__device__ float g_suf[(size_t)Bn * (NBK + 1) * Hn];  // block-suffix sums of v'

// ---------------- helpers ----------------------------------------------------
__device__ __forceinline__ float tf32r(float x) {
    uint32_t u;
    asm("cvt.rna.tf32.f32 %0, %1;" : "=r"(u) : "f"(x));
    return __uint_as_float(u);
}
__device__ __forceinline__ uint32_t smem_u32(const void* p) {
    uint32_t a;
    asm("{ .reg .u64 t; cvta.to.shared.u64 t, %1; cvt.u32.u64 %0, t; }" : "=r"(a) : "l"(p));
    return a;
}
__device__ __forceinline__ void cp16(uint32_t s, const void* g) {
    asm volatile("cp.async.ca.shared.global [%0], [%1], 16;" :: "r"(s), "l"(g));
}
#define CP_COMMIT() asm volatile("cp.async.commit_group;" ::: "memory")
#define CP_WAIT(n)  asm volatile("cp.async.wait_group %0;" :: "n"(n) : "memory")

__device__ __forceinline__ void mma8(float* d, const uint32_t* a, const uint32_t* b) {
    asm volatile(
        "mma.sync.aligned.m16n8k8.row.col.f32.tf32.tf32.f32 "
        "{%0,%1,%2,%3}, {%4,%5,%6,%7}, {%8,%9}, {%0,%1,%2,%3};"
        : "+f"(d[0]), "+f"(d[1]), "+f"(d[2]), "+f"(d[3])
        : "r"(a[0]), "r"(a[1]), "r"(a[2]), "r"(a[3]), "r"(b[0]), "r"(b[1]));
}

// ---------------- tensor-core GEMM (NT: A[M,K] x B[N,K] -> C[M,N]) -----------
// MODE 0: C = tf32(acc + bias[col])       (q projection)
// MODE 1: C = tf32(acc + bias[row])       (v^T projection)
// MODE 2: C = tf32(r>=c ? exp(acc*s):1)   triangular block launch (by>=bx)
// MODE 3: C = acc + Suf[by+1][col]        triangular K-loop (k-blocks 0..by)
#define LDS_S 36
#define STAGE_F (128 * LDS_S)
#define SMEM_BYTES (4 * STAGE_F * 4)

template <int MODE>
__global__ void __launch_bounds__(256, 2) mm_mma(
    const float* __restrict__ A, const float* __restrict__ B,
    const float* __restrict__ bias, float* __restrict__ C,
    int K, int ldA, int ldB, int ldC,
    long long zA, long long zB, long long zC)
{
    extern __shared__ float sm[];
    const int z = blockIdx.z;
    A += z * zA; B += z * zB; C += z * zC;

    // block coordinates
    int by, bx;
    if (MODE == 2) {
        const int idx = blockIdx.x;
        by = (int)((sqrtf(8.0f * idx + 1.0f) - 1.0f) * 0.5f);
        while ((by + 1) * (by + 2) / 2 <= idx) ++by;
        while (by * (by + 1) / 2 > idx) --by;
        bx = idx - by * (by + 1) / 2;
    } else {
        by = blockIdx.y; bx = blockIdx.x;
    }
    const int brow = by * 128, bcol = bx * 128;
    const int nk = (MODE == 3) ? 4 * (by + 1) : (K >> 5);

    const int tid  = threadIdx.x;
    const int wid  = tid >> 5, lane = tid & 31;
    const int wm   = wid & 1, wn = wid >> 1;      // warp tile: 64x32
    const int grp  = lane >> 2, tig = lane & 3;

    float* As[2] = { sm,             sm + STAGE_F };
    float* Bs[2] = { sm + 2*STAGE_F, sm + 3*STAGE_F };
    const uint32_t sA0 = smem_u32(As[0]), sB0 = smem_u32(Bs[0]);

    const int lr = tid >> 3, lc4 = (tid & 7) * 4;

    float acc[4][4][4];
#pragma unroll
    for (int i = 0; i < 4; i++)
#pragma unroll
        for (int j = 0; j < 4; j++)
#pragma unroll
            for (int k = 0; k < 4; k++) acc[i][j][k] = 0.0f;

    // prologue: stage 0
#pragma unroll
    for (int j = 0; j < 4; j++) {
        const int r = lr + 32 * j;
        cp16(sA0 + (r * LDS_S + lc4) * 4, A + (size_t)(brow + r) * ldA + lc4);
        cp16(sB0 + (r * LDS_S + lc4) * 4, B + (size_t)(bcol + r) * ldB + lc4);
    }
    CP_COMMIT();

    for (int i = 0; i < nk; i++) {
        const int cur = i & 1;
        if (i + 1 < nk) {
            const int nxt = cur ^ 1;
            const int k0 = (i + 1) * 32;
            const uint32_t sAn = sA0 + nxt * STAGE_F * 4;
            const uint32_t sBn = sB0 + nxt * STAGE_F * 4;
#pragma unroll
            for (int j = 0; j < 4; j++) {
                const int r = lr + 32 * j;
                cp16(sAn + (r * LDS_S + lc4) * 4, A + (size_t)(brow + r) * ldA + k0 + lc4);
                cp16(sBn + (r * LDS_S + lc4) * 4, B + (size_t)(bcol + r) * ldB + k0 + lc4);
            }
            CP_COMMIT();
            CP_WAIT(1);
        } else {
            CP_WAIT(0);
        }
        __syncthreads();

        const float* as = As[cur];
        const float* bs = Bs[cur];
#pragma unroll
        for (int k8 = 0; k8 < 4; k8++) {
            uint32_t afr[4][4], bfr[4][2];
#pragma unroll
            for (int mi = 0; mi < 4; mi++) {
                const float* p = as + (wm * 64 + mi * 16 + grp) * LDS_S + k8 * 8 + tig;
                afr[mi][0] = __float_as_uint(p[0]);
                afr[mi][1] = __float_as_uint(p[8 * LDS_S]);
                afr[mi][2] = __float_as_uint(p[4]);
                afr[mi][3] = __float_as_uint(p[8 * LDS_S + 4]);
            }
#pragma unroll
            for (int ni = 0; ni < 4; ni++) {
                const float* p = bs + (wn * 32 + ni * 8 + grp) * LDS_S + k8 * 8 + tig;
                bfr[ni][0] = __float_as_uint(p[0]);
                bfr[ni][1] = __float_as_uint(p[4]);
            }
#pragma unroll
            for (int mi = 0; mi < 4; mi++)
#pragma unroll
                for (int ni = 0; ni < 4; ni++)
                    mma8(acc[mi][ni], afr[mi], bfr[ni]);
        }
        __syncthreads();
    }

    // ---------------- epilogue ----------------
    const float* suf = (MODE == 3) ? bias + ((size_t)z * (NBK + 1) + by + 1) * Hn : nullptr;
#pragma unroll
    for (int mi = 0; mi < 4; mi++) {
        const int r0 = brow + wm * 64 + mi * 16 + grp;
#pragma unroll
        for (int half = 0; half < 2; half++) {
            const int r = r0 + half * 8;
            float rbias = 0.0f;
            if (MODE == 1) rbias = __ldg(&bias[r]);
#pragma unroll
            for (int ni = 0; ni < 4; ni++) {
                const int c = bcol + wn * 32 + ni * 8 + 2 * tig;
                float v0 = acc[mi][ni][half * 2 + 0];
                float v1 = acc[mi][ni][half * 2 + 1];
                if (MODE == 0) {
                    v0 = tf32r(v0 + __ldg(&bias[c]));
                    v1 = tf32r(v1 + __ldg(&bias[c + 1]));
                } else if (MODE == 1) {
                    v0 = tf32r(v0 + rbias);
                    v1 = tf32r(v1 + rbias);
                } else if (MODE == 2) {
                    v0 = tf32r((r >= c)     ? expf(v0 * ATTN_SCALE) : 1.0f);
                    v1 = tf32r((r >= c + 1) ? expf(v1 * ATTN_SCALE) : 1.0f);
                } else if (MODE == 3) {
                    v0 += __ldg(&suf[c]);
                    v1 += __ldg(&suf[c + 1]);
                }
                *reinterpret_cast<float2*>(C + (size_t)r * ldC + c) = make_float2(v0, v1);
            }
        }
    }
}

// ---------------- small kernels ---------------------------------------------
__global__ void __launch_bounds__(256) transpose_round(
    const float* __restrict__ src, float* __restrict__ dst, int R, int Cc)
{
    __shared__ float t[32][33];
    const int x = blockIdx.x * 32 + threadIdx.x;
    const int y0 = blockIdx.y * 32;
#pragma unroll
    for (int j = 0; j < 32; j += 8)
        t[threadIdx.y + j][threadIdx.x] = src[(size_t)(y0 + threadIdx.y + j) * Cc + x];
    __syncthreads();
    const int xo = y0 + threadIdx.x;
    const int yo0 = blockIdx.x * 32;
#pragma unroll
    for (int j = 0; j < 32; j += 8)
        dst[(size_t)(yo0 + threadIdx.y + j) * R + xo] = tf32r(t[threadIdx.x][threadIdx.y + j]);
}

__global__ void __launch_bounds__(256) round_x(const float* __restrict__ in, float* __restrict__ o)
{
    const size_t i = (size_t)blockIdx.x * 256 + threadIdx.x;
    float4 v = reinterpret_cast<const float4*>(in)[i];
    v.x = tf32r(v.x); v.y = tf32r(v.y); v.z = tf32r(v.z); v.w = tf32r(v.w);
    reinterpret_cast<float4*>(o)[i] = v;
}

// D[b*Tn+k] = (float)(k & ~127): rows above the diagonal block all contribute 1.0
__global__ void __launch_bounds__(256) init_d(float* __restrict__ D)
{
    const int i = blockIdx.x * 256 + threadIdx.x;
    D[i] = (float)((i & (Tn - 1)) & ~127);
}

// accumulate E-column sums over rows q >= (k & ~127) within a 256-row chunk
__global__ void __launch_bounds__(256) colsum(const float* __restrict__ E, float* __restrict__ D)
{
    const int k = blockIdx.x * 256 + threadIdx.x;
    const int b = blockIdx.y;
    const int r0 = blockIdx.z * 256;
    const int q0 = k & ~127;
    const int start = (r0 > q0) ? r0 : q0;
    const int end = r0 + 256;
    if (start >= end) return;
    const float* p = E + ((size_t)b * Tn + start) * Tn + k;
    float s = 0.0f;
    if (start == r0) {
#pragma unroll 8
        for (int q = 0; q < 256; q++) s += p[(size_t)q * Tn];
    } else {
        for (int q = start; q < end; q++) { s += *p; p += Tn; }
    }
    atomicAdd(&D[b * Tn + k], s);
}

// vt[h, b*T+t] /= D[b*T+t], round to tf32
__global__ void __launch_bounds__(256) vtscale(float* __restrict__ VT, const float* __restrict__ D)
{
    const size_t i4 = (size_t)blockIdx.x * 256 + threadIdx.x;
    float4 v = reinterpret_cast<float4*>(VT)[i4];
    const int col4 = (int)(i4 & (BT / 4 - 1));
    const float4 d = reinterpret_cast<const float4*>(D)[col4];
    v.x = tf32r(v.x / d.x); v.y = tf32r(v.y / d.y);
    v.z = tf32r(v.z / d.z); v.w = tf32r(v.w / d.w);
    reinterpret_cast<float4*>(VT)[i4] = v;
}

// block-suffix sums of v' rows: Suf[z][bi][n] = sum_{k >= bi*128} vt[n, z*Tn+k]
__global__ void __launch_bounds__(128) suffix_v(const float* __restrict__ VT, float* __restrict__ S)
{
    const int n = blockIdx.x, z = blockIdx.y;
    const int tid = threadIdx.x, wid = tid >> 5, lane = tid & 31;
    const float* row = VT + (size_t)n * BT + (size_t)z * Tn;
    __shared__ float chunk[NBK];
#pragma unroll
    for (int g = 0; g < NBK / 4; g++) {
        const int bi = g * 4 + wid;
        float v = 0.0f;
#pragma unroll
        for (int j = 0; j < 4; j++) v += row[bi * 128 + j * 32 + lane];
#pragma unroll
        for (int o = 16; o; o >>= 1) v += __shfl_xor_sync(0xFFFFFFFFu, v, o);
        if (lane == 0) chunk[bi] = v;
    }
    __syncthreads();
    if (tid == 0) {
        float s = 0.0f;
        S[((size_t)z * (NBK + 1) + NBK) * Hn + n] = 0.0f;
        for (int bi = NBK - 1; bi >= 0; bi--) {
            s += chunk[bi];
            S[((size_t)z * (NBK + 1) + bi) * Hn + n] = s;
        }
    }
}

// ---------------- host -------------------------------------------------------
extern "C" void kernel_launch(void* const* d_in, const int* in_sizes, int n_in,
                              void* d_out, int out_size)
{
    (void)in_sizes; (void)n_in; (void)out_size;
    const float* x  = (const float*)d_in[0];
    const float* Wq = (const float*)d_in[1];
    const float* bq = (const float*)d_in[2];
    const float* Wv = (const float*)d_in[3];
    const float* bv = (const float*)d_in[4];
    float* out = (float*)d_out;

    float *q, *vt, *e, *xr, *wtq, *wtv, *dI, *suf;
    cudaGetSymbolAddress((void**)&q,   g_q);
    cudaGetSymbolAddress((void**)&vt,  g_vt);
    cudaGetSymbolAddress((void**)&e,   g_e);
    cudaGetSymbolAddress((void**)&xr,  g_xr);
    cudaGetSymbolAddress((void**)&wtq, g_wtq);
    cudaGetSymbolAddress((void**)&wtv, g_wtv);
    cudaGetSymbolAddress((void**)&dI,  g_d);
    cudaGetSymbolAddress((void**)&suf, g_suf);

    cudaFuncSetAttribute(mm_mma<0>, cudaFuncAttributeMaxDynamicSharedMemorySize, SMEM_BYTES);
    cudaFuncSetAttribute(mm_mma<1>, cudaFuncAttributeMaxDynamicSharedMemorySize, SMEM_BYTES);
    cudaFuncSetAttribute(mm_mma<2>, cudaFuncAttributeMaxDynamicSharedMemorySize, SMEM_BYTES);
    cudaFuncSetAttribute(mm_mma<3>, cudaFuncAttributeMaxDynamicSharedMemorySize, SMEM_BYTES);

    // prep
    transpose_round<<<dim3(Hn / 32, En / 32), dim3(32, 8)>>>(Wq, wtq, En, Hn);
    transpose_round<<<dim3(Hn / 32, En / 32), dim3(32, 8)>>>(Wv, wtv, En, Hn);
    round_x<<<(int)(((size_t)BT * En / 4) / 256), 256>>>(x, xr);
    init_d<<<BT / 256, 256>>>(dI);

    // q = x @ Wq + bq                    [B*T, H]
    mm_mma<0><<<dim3(Hn / 128, BT / 128, 1), 256, SMEM_BYTES>>>(
        xr, wtq, bq, q, En, En, En, Hn, 0, 0, 0);
    // v^T = (x @ Wv + bv)^T              [H, B*T]
    mm_mma<1><<<dim3(BT / 128, Hn / 128, 1), 256, SMEM_BYTES>>>(
        wtv, xr, bv, vt, En, En, En, BT, 0, 0, 0);
    // E = exp(mask .* (q @ q^T) * s), lower-triangular blocks only (136/batch)
    mm_mma<2><<<dim3(NBK * (NBK + 1) / 2, 1, Bn), 256, SMEM_BYTES>>>(
        q, q, nullptr, e, Hn, Hn, Hn, Tn,
        (long long)Tn * Hn, (long long)Tn * Hn, (long long)Tn * Tn);
    // softmax denominators (analytic upper part + lower-block sums)
    colsum<<<dim3(Tn / 256, Bn, Tn / 256), 256>>>(e, dI);
    // fold 1/D into v^T columns, then block-suffix sums of v'
    vtscale<<<(int)(((size_t)Hn * BT / 4) / 256), 256>>>(vt, dI);
    suffix_v<<<dim3(Hn, Bn), 128>>>(vt, suf);
    // out = E_tri @ v' + Suf[by+1]       per batch, triangular K-loop
    mm_mma<3><<<dim3(Hn / 128, Tn / 128, Bn), 256, SMEM_BYTES>>>(
        e, vt, suf, out, Tn, Tn, BT, Hn,
        (long long)Tn * Tn, (long long)Tn, (long long)Tn * Hn);
}

// round 10
// speedup vs baseline: 1.3306x; 1.0016x over previous
#include <cuda_runtime.h>
#include <math.h>
#include <stdint.h>

#define Bn 4
#define Tn 2048
#define En 1024
#define Hn 2048
#define BT (Bn*Tn)
#define NBK (Tn/128)               // 16 blocks along T
#define ATTN_SCALE 0.022097086912079612f

// ---------------- scratch (static device memory; no cudaMalloc) -------------
__device__ float g_q  [(size_t)BT * Hn];   // q (tf32-rounded)
__device__ float g_vt [(size_t)Hn * BT];   // v^T as [H, B*T]
__device__ float g_e  [(size_t)BT * Tn];   // exp'd masked scores (lower blocks only)
__device__ float g_xr [(size_t)BT * En];   // x rounded to tf32
__device__ float g_wtq[(size_t)Hn * En];   // Wq^T rounded
__device__ float g_wtv[(size_t)Hn * En];   // Wv^T rounded
__device__ float g_d  [BT];                // softmax denominators
__device__ float g_suf[(size_t)Bn * (NBK + 1) * Hn];  // block-suffix sums of v'

// ---------------- helpers ----------------------------------------------------
__device__ __forceinline__ float tf32r(float x) {
    uint32_t u;
    asm("cvt.rna.tf32.f32 %0, %1;" : "=r"(u) : "f"(x));
    return __uint_as_float(u);
}
__device__ __forceinline__ uint32_t smem_u32(const void* p) {
    uint32_t a;
    asm("{ .reg .u64 t; cvta.to.shared.u64 t, %1; cvt.u32.u64 %0, t; }" : "=r"(a) : "l"(p));
    return a;
}
__device__ __forceinline__ void cp16(uint32_t s, const void* g) {
    asm volatile("cp.async.ca.shared.global [%0], [%1], 16;" :: "r"(s), "l"(g));
}
#define CP_COMMIT() asm volatile("cp.async.commit_group;" ::: "memory")
#define CP_WAIT(n)  asm volatile("cp.async.wait_group %0;" :: "n"(n) : "memory")

__device__ __forceinline__ void mma8(float* d, const uint32_t* a, const uint32_t* b) {
    asm volatile(
        "mma.sync.aligned.m16n8k8.row.col.f32.tf32.tf32.f32 "
        "{%0,%1,%2,%3}, {%4,%5,%6,%7}, {%8,%9}, {%0,%1,%2,%3};"
        : "+f"(d[0]), "+f"(d[1]), "+f"(d[2]), "+f"(d[3])
        : "r"(a[0]), "r"(a[1]), "r"(a[2]), "r"(a[3]), "r"(b[0]), "r"(b[1]));
}

// ---------------- tensor-core GEMM (NT: A[M,K] x B[N,K] -> C[M,N]) -----------
// MODE 0: C = tf32(acc + bias[col])       (q projection)
// MODE 1: C = tf32(acc + bias[row])       (v^T projection)
// MODE 2: C = tf32(r>=c ? exp(acc*s):1)   triangular block launch (by>=bx)
// MODE 3: C = acc + Suf[by+1][col]        triangular K-loop (k-blocks 0..by)
#define LDS_S 36
#define STAGE_F (128 * LDS_S)
#define SMEM_BYTES (4 * STAGE_F * 4)

template <int MODE>
__global__ void __launch_bounds__(256, 2) mm_mma(
    const float* __restrict__ A, const float* __restrict__ B,
    const float* __restrict__ bias, float* __restrict__ C,
    int K, int ldA, int ldB, int ldC,
    long long zA, long long zB, long long zC)
{
    extern __shared__ float sm[];
    const int z = blockIdx.z;
    A += z * zA; B += z * zB; C += z * zC;

    // block coordinates
    int by, bx;
    if (MODE == 2) {
        const int idx = blockIdx.x;
        by = (int)((sqrtf(8.0f * idx + 1.0f) - 1.0f) * 0.5f);
        while ((by + 1) * (by + 2) / 2 <= idx) ++by;
        while (by * (by + 1) / 2 > idx) --by;
        bx = idx - by * (by + 1) / 2;
    } else {
        by = blockIdx.y; bx = blockIdx.x;
    }
    const int brow = by * 128, bcol = bx * 128;
    const int nk = (MODE == 3) ? 4 * (by + 1) : (K >> 5);

    const int tid  = threadIdx.x;
    const int wid  = tid >> 5, lane = tid & 31;
    const int wm   = wid & 1, wn = wid >> 1;      // warp tile: 64x32
    const int grp  = lane >> 2, tig = lane & 3;

    float* As[2] = { sm,             sm + STAGE_F };
    float* Bs[2] = { sm + 2*STAGE_F, sm + 3*STAGE_F };
    const uint32_t sA0 = smem_u32(As[0]), sB0 = smem_u32(Bs[0]);

    const int lr = tid >> 3, lc4 = (tid & 7) * 4;

    float acc[4][4][4];
#pragma unroll
    for (int i = 0; i < 4; i++)
#pragma unroll
        for (int j = 0; j < 4; j++)
#pragma unroll
            for (int k = 0; k < 4; k++) acc[i][j][k] = 0.0f;

    // prologue: stage 0
#pragma unroll
    for (int j = 0; j < 4; j++) {
        const int r = lr + 32 * j;
        cp16(sA0 + (r * LDS_S + lc4) * 4, A + (size_t)(brow + r) * ldA + lc4);
        cp16(sB0 + (r * LDS_S + lc4) * 4, B + (size_t)(bcol + r) * ldB + lc4);
    }
    CP_COMMIT();

    for (int i = 0; i < nk; i++) {
        const int cur = i & 1;
        if (i + 1 < nk) {
            const int nxt = cur ^ 1;
            const int k0 = (i + 1) * 32;
            const uint32_t sAn = sA0 + nxt * STAGE_F * 4;
            const uint32_t sBn = sB0 + nxt * STAGE_F * 4;
#pragma unroll
            for (int j = 0; j < 4; j++) {
                const int r = lr + 32 * j;
                cp16(sAn + (r * LDS_S + lc4) * 4, A + (size_t)(brow + r) * ldA + k0 + lc4);
                cp16(sBn + (r * LDS_S + lc4) * 4, B + (size_t)(bcol + r) * ldB + k0 + lc4);
            }
            CP_COMMIT();
            CP_WAIT(1);
        } else {
            CP_WAIT(0);
        }
        __syncthreads();

        const float* as = As[cur];
        const float* bs = Bs[cur];
#pragma unroll
        for (int k8 = 0; k8 < 4; k8++) {
            uint32_t afr[4][4], bfr[4][2];
#pragma unroll
            for (int mi = 0; mi < 4; mi++) {
                const float* p = as + (wm * 64 + mi * 16 + grp) * LDS_S + k8 * 8 + tig;
                afr[mi][0] = __float_as_uint(p[0]);
                afr[mi][1] = __float_as_uint(p[8 * LDS_S]);
                afr[mi][2] = __float_as_uint(p[4]);
                afr[mi][3] = __float_as_uint(p[8 * LDS_S + 4]);
            }
#pragma unroll
            for (int ni = 0; ni < 4; ni++) {
                const float* p = bs + (wn * 32 + ni * 8 + grp) * LDS_S + k8 * 8 + tig;
                bfr[ni][0] = __float_as_uint(p[0]);
                bfr[ni][1] = __float_as_uint(p[4]);
            }
#pragma unroll
            for (int mi = 0; mi < 4; mi++)
#pragma unroll
                for (int ni = 0; ni < 4; ni++)
                    mma8(acc[mi][ni], afr[mi], bfr[ni]);
        }
        __syncthreads();
    }

    // ---------------- epilogue ----------------
    const float* suf = (MODE == 3) ? bias + ((size_t)z * (NBK + 1) + by + 1) * Hn : nullptr;
#pragma unroll
    for (int mi = 0; mi < 4; mi++) {
        const int r0 = brow + wm * 64 + mi * 16 + grp;
#pragma unroll
        for (int half = 0; half < 2; half++) {
            const int r = r0 + half * 8;
            float rbias = 0.0f;
            if (MODE == 1) rbias = __ldg(&bias[r]);
#pragma unroll
            for (int ni = 0; ni < 4; ni++) {
                const int c = bcol + wn * 32 + ni * 8 + 2 * tig;
                float v0 = acc[mi][ni][half * 2 + 0];
                float v1 = acc[mi][ni][half * 2 + 1];
                if (MODE == 0) {
                    v0 = tf32r(v0 + __ldg(&bias[c]));
                    v1 = tf32r(v1 + __ldg(&bias[c + 1]));
                } else if (MODE == 1) {
                    v0 = tf32r(v0 + rbias);
                    v1 = tf32r(v1 + rbias);
                } else if (MODE == 2) {
                    v0 = tf32r((r >= c)     ? expf(v0 * ATTN_SCALE) : 1.0f);
                    v1 = tf32r((r >= c + 1) ? expf(v1 * ATTN_SCALE) : 1.0f);
                } else if (MODE == 3) {
                    v0 += __ldg(&suf[c]);
                    v1 += __ldg(&suf[c + 1]);
                }
                *reinterpret_cast<float2*>(C + (size_t)r * ldC + c) = make_float2(v0, v1);
            }
        }
    }
}

// ---------------- small kernels ---------------------------------------------
__global__ void __launch_bounds__(256) transpose_round(
    const float* __restrict__ src, float* __restrict__ dst, int R, int Cc)
{
    __shared__ float t[32][33];
    const int x = blockIdx.x * 32 + threadIdx.x;
    const int y0 = blockIdx.y * 32;
#pragma unroll
    for (int j = 0; j < 32; j += 8)
        t[threadIdx.y + j][threadIdx.x] = src[(size_t)(y0 + threadIdx.y + j) * Cc + x];
    __syncthreads();
    const int xo = y0 + threadIdx.x;
    const int yo0 = blockIdx.x * 32;
#pragma unroll
    for (int j = 0; j < 32; j += 8)
        dst[(size_t)(yo0 + threadIdx.y + j) * R + xo] = tf32r(t[threadIdx.x][threadIdx.y + j]);
}

__global__ void __launch_bounds__(256) round_x(const float* __restrict__ in, float* __restrict__ o)
{
    const size_t i = (size_t)blockIdx.x * 256 + threadIdx.x;
    float4 v = reinterpret_cast<const float4*>(in)[i];
    v.x = tf32r(v.x); v.y = tf32r(v.y); v.z = tf32r(v.z); v.w = tf32r(v.w);
    reinterpret_cast<float4*>(o)[i] = v;
}

// D[b*Tn+k] = (float)(k & ~127): rows above the diagonal block all contribute 1.0
__global__ void __launch_bounds__(256) init_d(float* __restrict__ D)
{
    const int i = blockIdx.x * 256 + threadIdx.x;
    D[i] = (float)((i & (Tn - 1)) & ~127);
}

// accumulate E-column sums over rows q >= (k & ~127) within a 256-row chunk
__global__ void __launch_bounds__(256) colsum(const float* __restrict__ E, float* __restrict__ D)
{
    const int k = blockIdx.x * 256 + threadIdx.x;
    const int b = blockIdx.y;
    const int r0 = blockIdx.z * 256;
    const int q0 = k & ~127;
    const int start = (r0 > q0) ? r0 : q0;
    const int end = r0 + 256;
    if (start >= end) return;
    const float* p = E + ((size_t)b * Tn + start) * Tn + k;
    float s = 0.0f;
    if (start == r0) {
#pragma unroll 8
        for (int q = 0; q < 256; q++) s += p[(size_t)q * Tn];
    } else {
        for (int q = start; q < end; q++) { s += *p; p += Tn; }
    }
    atomicAdd(&D[b * Tn + k], s);
}

// vt[h, b*T+t] /= D[b*T+t], round to tf32
__global__ void __launch_bounds__(256) vtscale(float* __restrict__ VT, const float* __restrict__ D)
{
    const size_t i4 = (size_t)blockIdx.x * 256 + threadIdx.x;
    float4 v = reinterpret_cast<float4*>(VT)[i4];
    const int col4 = (int)(i4 & (BT / 4 - 1));
    const float4 d = reinterpret_cast<const float4*>(D)[col4];
    v.x = tf32r(v.x / d.x); v.y = tf32r(v.y / d.y);
    v.z = tf32r(v.z / d.z); v.w = tf32r(v.w / d.w);
    reinterpret_cast<float4*>(VT)[i4] = v;
}

// block-suffix sums of v' rows: Suf[z][bi][n] = sum_{k >= bi*128} vt[n, z*Tn+k]
__global__ void __launch_bounds__(128) suffix_v(const float* __restrict__ VT, float* __restrict__ S)
{
    const int n = blockIdx.x, z = blockIdx.y;
    const int tid = threadIdx.x, wid = tid >> 5, lane = tid & 31;
    const float* row = VT + (size_t)n * BT + (size_t)z * Tn;
    __shared__ float chunk[NBK];
#pragma unroll
    for (int g = 0; g < NBK / 4; g++) {
        const int bi = g * 4 + wid;
        float v = 0.0f;
#pragma unroll
        for (int j = 0; j < 4; j++) v += row[bi * 128 + j * 32 + lane];
#pragma unroll
        for (int o = 16; o; o >>= 1) v += __shfl_xor_sync(0xFFFFFFFFu, v, o);
        if (lane == 0) chunk[bi] = v;
    }
    __syncthreads();
    if (tid == 0) {
        float s = 0.0f;
        S[((size_t)z * (NBK + 1) + NBK) * Hn + n] = 0.0f;
        for (int bi = NBK - 1; bi >= 0; bi--) {
            s += chunk[bi];
            S[((size_t)z * (NBK + 1) + bi) * Hn + n] = s;
        }
    }
}

// ---------------- host -------------------------------------------------------
extern "C" void kernel_launch(void* const* d_in, const int* in_sizes, int n_in,
                              void* d_out, int out_size)
{
    (void)in_sizes; (void)n_in; (void)out_size;
    const float* x  = (const float*)d_in[0];
    const float* Wq = (const float*)d_in[1];
    const float* bq = (const float*)d_in[2];
    const float* Wv = (const float*)d_in[3];
    const float* bv = (const float*)d_in[4];
    float* out = (float*)d_out;

    float *q, *vt, *e, *xr, *wtq, *wtv, *dI, *suf;
    cudaGetSymbolAddress((void**)&q,   g_q);
    cudaGetSymbolAddress((void**)&vt,  g_vt);
    cudaGetSymbolAddress((void**)&e,   g_e);
    cudaGetSymbolAddress((void**)&xr,  g_xr);
    cudaGetSymbolAddress((void**)&wtq, g_wtq);
    cudaGetSymbolAddress((void**)&wtv, g_wtv);
    cudaGetSymbolAddress((void**)&dI,  g_d);
    cudaGetSymbolAddress((void**)&suf, g_suf);

    cudaFuncSetAttribute(mm_mma<0>, cudaFuncAttributeMaxDynamicSharedMemorySize, SMEM_BYTES);
    cudaFuncSetAttribute(mm_mma<1>, cudaFuncAttributeMaxDynamicSharedMemorySize, SMEM_BYTES);
    cudaFuncSetAttribute(mm_mma<2>, cudaFuncAttributeMaxDynamicSharedMemorySize, SMEM_BYTES);
    cudaFuncSetAttribute(mm_mma<3>, cudaFuncAttributeMaxDynamicSharedMemorySize, SMEM_BYTES);

    // prep
    transpose_round<<<dim3(Hn / 32, En / 32), dim3(32, 8)>>>(Wq, wtq, En, Hn);
    transpose_round<<<dim3(Hn / 32, En / 32), dim3(32, 8)>>>(Wv, wtv, En, Hn);
    round_x<<<(int)(((size_t)BT * En / 4) / 256), 256>>>(x, xr);
    init_d<<<BT / 256, 256>>>(dI);

    // q = x @ Wq + bq                    [B*T, H]
    mm_mma<0><<<dim3(Hn / 128, BT / 128, 1), 256, SMEM_BYTES>>>(
        xr, wtq, bq, q, En, En, En, Hn, 0, 0, 0);
    // v^T = (x @ Wv + bv)^T              [H, B*T]
    mm_mma<1><<<dim3(BT / 128, Hn / 128, 1), 256, SMEM_BYTES>>>(
        wtv, xr, bv, vt, En, En, En, BT, 0, 0, 0);
    // E = exp(mask .* (q @ q^T) * s), lower-triangular blocks only (136/batch)
    mm_mma<2><<<dim3(NBK * (NBK + 1) / 2, 1, Bn), 256, SMEM_BYTES>>>(
        q, q, nullptr, e, Hn, Hn, Hn, Tn,
        (long long)Tn * Hn, (long long)Tn * Hn, (long long)Tn * Tn);
    // softmax denominators (analytic upper part + lower-block sums)
    colsum<<<dim3(Tn / 256, Bn, Tn / 256), 256>>>(e, dI);
    // fold 1/D into v^T columns, then block-suffix sums of v'
    vtscale<<<(int)(((size_t)Hn * BT / 4) / 256), 256>>>(vt, dI);
    suffix_v<<<dim3(Hn, Bn), 128>>>(vt, suf);
    // out = E_tri @ v' + Suf[by+1]       per batch, triangular K-loop
    mm_mma<3><<<dim3(Hn / 128, Tn / 128, Bn), 256, SMEM_BYTES>>>(
        e, vt, suf, out, Tn, Tn, BT, Hn,
        (long long)Tn * Tn, (long long)Tn, (long long)Tn * Hn);
}

// round 13
// speedup vs baseline: 2.3069x; 1.7337x over previous
#include <cuda_runtime.h>
#include <cuda_fp16.h>
#include <math.h>
#include <stdint.h>

#define Bn 4
#define Tn 2048
#define En 1024
#define Hn 2048
#define BT (Bn*Tn)
#define NBK (Tn/128)               // 16 blocks along T
#define ATTN_SCALE 0.022097086912079612f
// E is stored scaled by ALPHA = 2^-18 to fit fp16; alpha cancels in E*v/D.
#define ALPHA     3.814697265625e-6f
#define LN_ALPHA (-12.476649250079015f)
// vt2 = BETA * v / D' to keep it in fp16 normal range
#define BETA      32.0f
#define INV_BETA  0.03125f
#define SUF_SCALE (ALPHA / BETA)

// ---------------- scratch (static device memory; no cudaMalloc) -------------
__device__ __half g_q  [(size_t)BT * Hn];   // q (fp16)                 32MB
__device__ __half g_vt [(size_t)Hn * BT];   // v^T as [H, B*T]          32MB
__device__ __half g_e  [(size_t)BT * Tn];   // alpha * exp'd scores     32MB
__device__ __half g_xr [(size_t)BT * En];   // x rounded to fp16        16MB
__device__ __half g_wtq[(size_t)Hn * En];   // Wq^T fp16                 4MB
__device__ __half g_wtv[(size_t)Hn * En];   // Wv^T fp16                 4MB
__device__ float  g_d  [BT];                // scaled softmax denominators D'
__device__ float  g_suf[(size_t)Bn * (NBK + 1) * Hn];  // suffix sums (alpha-scaled)

// ---------------- helpers ----------------------------------------------------
__device__ __forceinline__ uint32_t smem_u32(const void* p) {
    uint32_t a;
    asm("{ .reg .u64 t; cvta.to.shared.u64 t, %1; cvt.u32.u64 %0, t; }" : "=r"(a) : "l"(p));
    return a;
}
__device__ __forceinline__ uint32_t h2_as_u32(__half2 h) {
    return *reinterpret_cast<uint32_t*>(&h);
}
__device__ __forceinline__ void cp16(uint32_t s, const void* g) {
    asm volatile("cp.async.ca.shared.global [%0], [%1], 16;" :: "r"(s), "l"(g));
}
#define CP_COMMIT() asm volatile("cp.async.commit_group;" ::: "memory")
#define CP_WAIT(n)  asm volatile("cp.async.wait_group %0;" :: "n"(n) : "memory")

__device__ __forceinline__ void mma16(float* d, const uint32_t* a, const uint32_t* b) {
    asm volatile(
        "mma.sync.aligned.m16n8k16.row.col.f32.f16.f16.f32 "
        "{%0,%1,%2,%3}, {%4,%5,%6,%7}, {%8,%9}, {%0,%1,%2,%3};"
        : "+f"(d[0]), "+f"(d[1]), "+f"(d[2]), "+f"(d[3])
        : "r"(a[0]), "r"(a[1]), "r"(a[2]), "r"(a[3]), "r"(b[0]), "r"(b[1]));
}

// ---------------- fp16 tensor-core GEMM (NT: A[M,K] x B[N,K] -> C[M,N]) ------
// MODE 0: C(h) = h(acc + bias[col])                  (q projection)
// MODE 1: C(h) = h(acc + bias[row])                  (v^T projection)
// MODE 2: C(h) = h(r>=c ? a*exp(acc*s) : a), tri launch, fused column sums
// MODE 3: C(f) = acc/BETA + Suf[by+1][col],  triangular K-loop (k-blocks 0..by)
#define SROW 40                     // halfs per smem row (80B, conflict-free)
#define STAGE_H (128 * SROW)        // 5120 halfs = 10240B per operand stage
#define NST 3
#define SMEM_BYTES (2 * NST * STAGE_H * 2 + 512)

template <int MODE>
__global__ void __launch_bounds__(256, 2) mm_h(
    const __half* __restrict__ A, const __half* __restrict__ B,
    const float* __restrict__ bias, void* __restrict__ Cv,
    float* __restrict__ aux,
    int K, int ldA, int ldB, int ldC,
    long long zA, long long zB, long long zC)
{
    extern __shared__ __half smh[];
    const int z = blockIdx.z;
    A += z * zA; B += z * zB;

    // block coordinates
    int by, bx;
    if (MODE == 2) {
        const int idx = blockIdx.x;
        by = (int)((sqrtf(8.0f * idx + 1.0f) - 1.0f) * 0.5f);
        while ((by + 1) * (by + 2) / 2 <= idx) ++by;
        while (by * (by + 1) / 2 > idx) --by;
        bx = idx - by * (by + 1) / 2;
    } else {
        by = blockIdx.y; bx = blockIdx.x;
    }
    const int brow = by * 128, bcol = bx * 128;
    const int nk = (MODE == 3) ? 4 * (by + 1) : (K >> 5);

    __half* As = smh;
    __half* Bs = smh + NST * STAGE_H;
    float*  cs = (float*)(smh + 2 * NST * STAGE_H);   // 128-col sums (MODE 2)

    const int tid = threadIdx.x, wid = tid >> 5, lane = tid & 31;
    const int wm = wid & 1, wn = wid >> 1;            // warp tile 64x32
    const int grp = lane >> 2, tig = lane & 3;

    // tile loader: 128 rows x 32 halfs; 16B chunks; thread -> (row, chunk) x2
    const int l_r = tid >> 2, l_cc = tid & 3;

    float acc[4][4][4];
#pragma unroll
    for (int i = 0; i < 4; i++)
#pragma unroll
        for (int j = 0; j < 4; j++)
#pragma unroll
            for (int k = 0; k < 4; k++) acc[i][j][k] = 0.0f;

    const uint32_t sA0 = smem_u32(As), sB0 = smem_u32(Bs);

#define LOAD_STAGE(s, kc) do { \
        const __half* Ag = A + (size_t)brow * ldA + (kc) * 32; \
        const __half* Bg = B + (size_t)bcol * ldB + (kc) * 32; \
        const uint32_t sa = sA0 + (s) * STAGE_H * 2; \
        const uint32_t sb = sB0 + (s) * STAGE_H * 2; \
        _Pragma("unroll") \
        for (int h = 0; h < 2; h++) { \
            const int r = l_r + h * 64; \
            cp16(sa + r * 80 + l_cc * 16, Ag + (size_t)r * ldA + l_cc * 8); \
            cp16(sb + r * 80 + l_cc * 16, Bg + (size_t)r * ldB + l_cc * 8); \
        } \
    } while (0)

    // prologue: stages 0,1
    LOAD_STAGE(0, 0); CP_COMMIT();
    if (nk > 1) LOAD_STAGE(1, 1);
    CP_COMMIT();

    for (int i = 0; i < nk; i++) {
        CP_WAIT(1);
        __syncthreads();
        if (i + 2 < nk) LOAD_STAGE((i + 2) % NST, i + 2);
        CP_COMMIT();

        const __half* as = As + (i % NST) * STAGE_H;
        const __half* bs = Bs + (i % NST) * STAGE_H;
#pragma unroll
        for (int k16 = 0; k16 < 2; k16++) {
            uint32_t afr[4][4], bfr[4][2];
#pragma unroll
            for (int mi = 0; mi < 4; mi++) {
                const __half* p = as + (wm * 64 + mi * 16 + grp) * SROW + k16 * 16 + 2 * tig;
                afr[mi][0] = *(const uint32_t*)(p);
                afr[mi][1] = *(const uint32_t*)(p + 8 * SROW);
                afr[mi][2] = *(const uint32_t*)(p + 8);
                afr[mi][3] = *(const uint32_t*)(p + 8 * SROW + 8);
            }
#pragma unroll
            for (int ni = 0; ni < 4; ni++) {
                const __half* p = bs + (wn * 32 + ni * 8 + grp) * SROW + k16 * 16 + 2 * tig;
                bfr[ni][0] = *(const uint32_t*)(p);
                bfr[ni][1] = *(const uint32_t*)(p + 8);
            }
#pragma unroll
            for (int mi = 0; mi < 4; mi++)
#pragma unroll
                for (int ni = 0; ni < 4; ni++)
                    mma16(acc[mi][ni], afr[mi], bfr[ni]);
        }
    }

    // ---------------- epilogue ----------------
    float colacc[4][2];
    if (MODE == 2) {
#pragma unroll
        for (int ni = 0; ni < 4; ni++) { colacc[ni][0] = 0.0f; colacc[ni][1] = 0.0f; }
        if (tid < 128) cs[tid] = 0.0f;
    }
    const float* suf = (MODE == 3) ? bias + ((size_t)z * (NBK + 1) + by + 1) * Hn : nullptr;

#pragma unroll
    for (int mi = 0; mi < 4; mi++) {
        const int r0 = brow + wm * 64 + mi * 16 + grp;
#pragma unroll
        for (int half = 0; half < 2; half++) {
            const int r = r0 + half * 8;
            float rbias = 0.0f;
            if (MODE == 1) rbias = __ldg(&bias[r]);
#pragma unroll
            for (int ni = 0; ni < 4; ni++) {
                const int c = bcol + wn * 32 + ni * 8 + 2 * tig;
                float v0 = acc[mi][ni][half * 2 + 0];
                float v1 = acc[mi][ni][half * 2 + 1];
                if (MODE == 0) {
                    v0 += __ldg(&bias[c]); v1 += __ldg(&bias[c + 1]);
                } else if (MODE == 1) {
                    v0 += rbias; v1 += rbias;
                } else if (MODE == 2) {
                    // E' = alpha * exp(score*s)  (alpha folded into the exponent);
                    // masked-out entries are alpha * 1
                    v0 = (r >= c)     ? __expf(fmaf(v0, ATTN_SCALE, LN_ALPHA)) : ALPHA;
                    v1 = (r >= c + 1) ? __expf(fmaf(v1, ATTN_SCALE, LN_ALPHA)) : ALPHA;
                }
                if (MODE == 3) {
                    float* Cf = (float*)Cv + (size_t)z * zC;
                    v0 = fmaf(v0, INV_BETA, __ldg(&suf[c]));
                    v1 = fmaf(v1, INV_BETA, __ldg(&suf[c + 1]));
                    *reinterpret_cast<float2*>(Cf + (size_t)r * ldC + c) = make_float2(v0, v1);
                } else {
                    __half2 hv = __floats2half2_rn(v0, v1);
                    if (MODE == 2) {
                        const float2 f = __half22float2(hv);
                        colacc[ni][0] += f.x; colacc[ni][1] += f.y;
                    }
                    __half* Ch = (__half*)Cv + (size_t)z * zC;
                    *reinterpret_cast<__half2*>(Ch + (size_t)r * ldC + c) = hv;
                }
            }
        }
    }

    if (MODE == 2) {
        __syncthreads();
#pragma unroll
        for (int ni = 0; ni < 4; ni++) {
            atomicAdd(&cs[wn * 32 + ni * 8 + 2 * tig],     colacc[ni][0]);
            atomicAdd(&cs[wn * 32 + ni * 8 + 2 * tig + 1], colacc[ni][1]);
        }
        __syncthreads();
        if (tid < 128) atomicAdd(&aux[(size_t)z * Tn + bcol + tid], cs[tid]);
    }
}

// ---------------- small kernels ---------------------------------------------
// transpose [R, Cc] f32 -> [Cc, R] fp16
__global__ void __launch_bounds__(256) transpose_h(
    const float* __restrict__ src, __half* __restrict__ dst, int R, int Cc)
{
    __shared__ float t[32][33];
    const int x = blockIdx.x * 32 + threadIdx.x;
    const int y0 = blockIdx.y * 32;
#pragma unroll
    for (int j = 0; j < 32; j += 8)
        t[threadIdx.y + j][threadIdx.x] = src[(size_t)(y0 + threadIdx.y + j) * Cc + x];
    __syncthreads();
    const int xo = y0 + threadIdx.x;
    const int yo0 = blockIdx.x * 32;
#pragma unroll
    for (int j = 0; j < 32; j += 8)
        dst[(size_t)(yo0 + threadIdx.y + j) * R + xo] = __float2half_rn(t[threadIdx.x][threadIdx.y + j]);
}

// f32 -> fp16 (4 elems/thread)
__global__ void __launch_bounds__(256) round_xh(const float* __restrict__ in, __half* __restrict__ o)
{
    const size_t i = (size_t)blockIdx.x * 256 + threadIdx.x;
    float4 v = reinterpret_cast<const float4*>(in)[i];
    uint2 w;
    w.x = h2_as_u32(__floats2half2_rn(v.x, v.y));
    w.y = h2_as_u32(__floats2half2_rn(v.z, v.w));
    reinterpret_cast<uint2*>(o)[i] = w;
}

// D'[b*Tn+k] = ALPHA * (k & ~127): analytic contribution of the all-ones rows
__global__ void __launch_bounds__(256) init_d(float* __restrict__ D)
{
    const int i = blockIdx.x * 256 + threadIdx.x;
    D[i] = ALPHA * (float)((i & (Tn - 1)) & ~127);
}

// vt2[h, b*T+t] = BETA * vt / D'[b*T+t]   (8 halfs/thread)
__global__ void __launch_bounds__(256) vtscale_h(__half* __restrict__ VT, const float* __restrict__ D)
{
    const size_t i8 = (size_t)blockIdx.x * 256 + threadIdx.x;
    uint4 raw = reinterpret_cast<uint4*>(VT)[i8];
    __half2* hp = reinterpret_cast<__half2*>(&raw);
    const int base = (int)((i8 * 8) & (BT - 1));
    const float4 d0 = *reinterpret_cast<const float4*>(D + base);
    const float4 d1 = *reinterpret_cast<const float4*>(D + base + 4);
    float2 f;
    f = __half22float2(hp[0]); hp[0] = __floats2half2_rn(BETA * f.x / d0.x, BETA * f.y / d0.y);
    f = __half22float2(hp[1]); hp[1] = __floats2half2_rn(BETA * f.x / d0.z, BETA * f.y / d0.w);
    f = __half22float2(hp[2]); hp[2] = __floats2half2_rn(BETA * f.x / d1.x, BETA * f.y / d1.y);
    f = __half22float2(hp[3]); hp[3] = __floats2half2_rn(BETA * f.x / d1.z, BETA * f.y / d1.w);
    reinterpret_cast<uint4*>(VT)[i8] = raw;
}

// Suf[z][bi][n] = ALPHA * sum_{k >= bi*128} v[n,k]/D'[k]  = (ALPHA/BETA)*sum vt2
__global__ void __launch_bounds__(128) suffix_v(const __half* __restrict__ VT, float* __restrict__ S)
{
    const int n = blockIdx.x, z = blockIdx.y;
    const int tid = threadIdx.x, wid = tid >> 5, lane = tid & 31;
    const __half* row = VT + (size_t)n * BT + (size_t)z * Tn;
    __shared__ float chunk[NBK];
#pragma unroll
    for (int g = 0; g < NBK / 4; g++) {
        const int bi = g * 4 + wid;
        float v = 0.0f;
#pragma unroll
        for (int j = 0; j < 4; j++) v += __half2float(row[bi * 128 + j * 32 + lane]);
#pragma unroll
        for (int o = 16; o; o >>= 1) v += __shfl_xor_sync(0xFFFFFFFFu, v, o);
        if (lane == 0) chunk[bi] = v;
    }
    __syncthreads();
    if (tid == 0) {
        float s = 0.0f;
        S[((size_t)z * (NBK + 1) + NBK) * Hn + n] = 0.0f;
        for (int bi = NBK - 1; bi >= 0; bi--) {
            s += chunk[bi];
            S[((size_t)z * (NBK + 1) + bi) * Hn + n] = s * SUF_SCALE;
        }
    }
}

// ---------------- host -------------------------------------------------------
extern "C" void kernel_launch(void* const* d_in, const int* in_sizes, int n_in,
                              void* d_out, int out_size)
{
    (void)in_sizes; (void)n_in; (void)out_size;
    const float* x  = (const float*)d_in[0];
    const float* Wq = (const float*)d_in[1];
    const float* bq = (const float*)d_in[2];
    const float* Wv = (const float*)d_in[3];
    const float* bv = (const float*)d_in[4];
    float* out = (float*)d_out;

    __half *q, *vt, *e, *xr, *wtq, *wtv;
    float *dI, *suf;
    cudaGetSymbolAddress((void**)&q,   g_q);
    cudaGetSymbolAddress((void**)&vt,  g_vt);
    cudaGetSymbolAddress((void**)&e,   g_e);
    cudaGetSymbolAddress((void**)&xr,  g_xr);
    cudaGetSymbolAddress((void**)&wtq, g_wtq);
    cudaGetSymbolAddress((void**)&wtv, g_wtv);
    cudaGetSymbolAddress((void**)&dI,  g_d);
    cudaGetSymbolAddress((void**)&suf, g_suf);

    cudaFuncSetAttribute(mm_h<0>, cudaFuncAttributeMaxDynamicSharedMemorySize, SMEM_BYTES);
    cudaFuncSetAttribute(mm_h<1>, cudaFuncAttributeMaxDynamicSharedMemorySize, SMEM_BYTES);
    cudaFuncSetAttribute(mm_h<2>, cudaFuncAttributeMaxDynamicSharedMemorySize, SMEM_BYTES);
    cudaFuncSetAttribute(mm_h<3>, cudaFuncAttributeMaxDynamicSharedMemorySize, SMEM_BYTES);

    // prep: transpose+convert weights, convert x, init denominators
    transpose_h<<<dim3(Hn / 32, En / 32), dim3(32, 8)>>>(Wq, wtq, En, Hn);
    transpose_h<<<dim3(Hn / 32, En / 32), dim3(32, 8)>>>(Wv, wtv, En, Hn);
    round_xh<<<(int)(((size_t)BT * En / 4) / 256), 256>>>(x, xr);
    init_d<<<BT / 256, 256>>>(dI);

    // q = x @ Wq + bq                    [B*T, H] fp16
    mm_h<0><<<dim3(Hn / 128, BT / 128, 1), 256, SMEM_BYTES>>>(
        xr, wtq, bq, q, nullptr, En, En, En, Hn, 0, 0, 0);
    // v^T = (x @ Wv + bv)^T              [H, B*T] fp16
    mm_h<1><<<dim3(BT / 128, Hn / 128, 1), 256, SMEM_BYTES>>>(
        wtv, xr, bv, vt, nullptr, En, En, En, BT, 0, 0, 0);
    // E' = alpha*exp(mask .* (q@q^T)*s), lower-tri blocks, fused column sums
    mm_h<2><<<dim3(NBK * (NBK + 1) / 2, 1, Bn), 256, SMEM_BYTES>>>(
        q, q, nullptr, e, dI, Hn, Hn, Hn, Tn,
        (long long)Tn * Hn, (long long)Tn * Hn, (long long)Tn * Tn);
    // fold BETA/D' into v^T columns, then alpha-scaled block-suffix sums
    vtscale_h<<<(int)(((size_t)Hn * BT / 8) / 256), 256>>>(vt, dI);
    suffix_v<<<dim3(Hn, Bn), 128>>>(vt, suf);
    // out = E'_tri @ vt2 / BETA + Suf[by+1]   per batch, triangular K-loop
    mm_h<3><<<dim3(Hn / 128, Tn / 128, Bn), 256, SMEM_BYTES>>>(
        e, vt, suf, out, nullptr, Tn, Tn, BT, Hn,
        (long long)Tn * Tn, (long long)Tn, (long long)Tn * Hn);
}

// round 14
// speedup vs baseline: 2.7452x; 1.1900x over previous
#include <cuda_runtime.h>
#include <cuda_fp16.h>
#include <math.h>
#include <stdint.h>

#define Bn 4
#define Tn 2048
#define En 1024
#define Hn 2048
#define BT (Bn*Tn)
#define NBK (Tn/128)               // 16 blocks along T
#define ATTN_SCALE 0.022097086912079612f
// E is stored scaled by ALPHA = 2^-18 to fit fp16; alpha cancels in E*v/D.
#define ALPHA     3.814697265625e-6f
#define LN_ALPHA (-12.476649250079015f)
// vt2 = BETA * v / D' to keep it in fp16 normal range
#define BETA      32.0f
#define INV_BETA  0.03125f
#define SUF_SCALE (ALPHA / BETA)

// ---------------- scratch (static device memory; no cudaMalloc) -------------
__device__ __half g_q  [(size_t)BT * Hn];   // q (fp16)                 32MB
__device__ __half g_vt [(size_t)Hn * BT];   // v^T as [H, B*T]          32MB
__device__ __half g_e  [(size_t)BT * Tn];   // alpha * exp'd scores     32MB
__device__ __half g_xr [(size_t)BT * En];   // x rounded to fp16        16MB
__device__ __half g_wtq[(size_t)Hn * En];   // Wq^T fp16                 4MB
__device__ __half g_wtv[(size_t)Hn * En];   // Wv^T fp16                 4MB
__device__ float  g_d  [BT];                // scaled softmax denominators D'
__device__ float  g_suf[(size_t)Bn * (NBK + 1) * Hn];  // suffix sums (alpha-scaled)

// ---------------- helpers ----------------------------------------------------
__device__ __forceinline__ uint32_t smem_u32(const void* p) {
    uint32_t a;
    asm("{ .reg .u64 t; cvta.to.shared.u64 t, %1; cvt.u32.u64 %0, t; }" : "=r"(a) : "l"(p));
    return a;
}
__device__ __forceinline__ uint32_t h2_as_u32(__half2 h) {
    return *reinterpret_cast<uint32_t*>(&h);
}
__device__ __forceinline__ void cp16(uint32_t s, const void* g) {
    asm volatile("cp.async.ca.shared.global [%0], [%1], 16;" :: "r"(s), "l"(g));
}
#define CP_COMMIT() asm volatile("cp.async.commit_group;" ::: "memory")
#define CP_WAIT(n)  asm volatile("cp.async.wait_group %0;" :: "n"(n) : "memory")

__device__ __forceinline__ void ldm_x4(uint32_t* r, uint32_t addr) {
    asm volatile("ldmatrix.sync.aligned.m8n8.x4.shared.b16 {%0,%1,%2,%3}, [%4];"
        : "=r"(r[0]), "=r"(r[1]), "=r"(r[2]), "=r"(r[3]) : "r"(addr));
}
__device__ __forceinline__ void mma16(float* d, const uint32_t* a, const uint32_t* b) {
    asm volatile(
        "mma.sync.aligned.m16n8k16.row.col.f32.f16.f16.f32 "
        "{%0,%1,%2,%3}, {%4,%5,%6,%7}, {%8,%9}, {%0,%1,%2,%3};"
        : "+f"(d[0]), "+f"(d[1]), "+f"(d[2]), "+f"(d[3])
        : "r"(a[0]), "r"(a[1]), "r"(a[2]), "r"(a[3]), "r"(b[0]), "r"(b[1]));
}

// ---------------- fp16 tensor-core GEMM (NT: A[M,K] x B[N,K] -> C[M,N]) ------
// MODE 0: C(h) = h(acc + bias[col])                  (q projection)
// MODE 1: C(h) = h(acc + bias[row])                  (v^T projection)
// MODE 2: C(h) = h(r>=c ? a*exp(acc*s) : a), tri launch, fused column sums
// MODE 3: C(f) = acc/BETA + Suf[by+1][col],  triangular K-loop (k-blocks 0..by)
#define SROW 40                     // halfs per smem row (80B, conflict-free)
#define STAGE_H (128 * SROW)        // 5120 halfs per operand stage
#define STAGE_B (STAGE_H * 2)       // 10240 bytes
#define NST 4
#define SMEM_BYTES (2 * NST * STAGE_B + 512)

template <int MODE>
__global__ void __launch_bounds__(256, 2) mm_h(
    const __half* __restrict__ A, const __half* __restrict__ B,
    const float* __restrict__ bias, void* __restrict__ Cv,
    float* __restrict__ aux,
    int K, int ldA, int ldB, int ldC,
    long long zA, long long zB, long long zC)
{
    extern __shared__ __half smh[];
    const int z = blockIdx.z;
    A += z * zA; B += z * zB;

    // block coordinates
    int by, bx;
    if (MODE == 2) {
        const int idx = blockIdx.x;
        by = (int)((sqrtf(8.0f * idx + 1.0f) - 1.0f) * 0.5f);
        while ((by + 1) * (by + 2) / 2 <= idx) ++by;
        while (by * (by + 1) / 2 > idx) --by;
        bx = idx - by * (by + 1) / 2;
    } else {
        by = blockIdx.y; bx = blockIdx.x;
    }
    const int brow = by * 128, bcol = bx * 128;
    const int nk = (MODE == 3) ? 4 * (by + 1) : (K >> 5);

    __half* As = smh;
    __half* Bs = smh + NST * STAGE_H;
    float*  cs = (float*)(smh + 2 * NST * STAGE_H);   // 128-col sums (MODE 2)

    const int tid = threadIdx.x, wid = tid >> 5, lane = tid & 31;
    const int wm = wid & 1, wn = wid >> 1;            // warp tile 64x32
    const int grp = lane >> 2, tig = lane & 3;

    // tile loader: 128 rows x 32 halfs; 16B chunks; thread -> (row, chunk) x2
    const int l_r = tid >> 2, l_cc = tid & 3;

    float acc[4][4][4];
#pragma unroll
    for (int i = 0; i < 4; i++)
#pragma unroll
        for (int j = 0; j < 4; j++)
#pragma unroll
            for (int k = 0; k < 4; k++) acc[i][j][k] = 0.0f;

    const uint32_t sA0 = smem_u32(As), sB0 = smem_u32(Bs);

    // ldmatrix lane-base addresses (bytes); 80B row stride is phase-conflict-free
    const uint32_t aAddr = sA0 + (wm * 64 + (lane & 15)) * 80 + ((lane >> 4) << 4);
    const uint32_t bAddr = sB0 + (wn * 32 + ((lane >> 4) << 3) + (lane & 7)) * 80
                         + (((lane >> 3) & 1) << 4);

#define LOAD_STAGE(s, kc) do { \
        const __half* Ag = A + (size_t)brow * ldA + (kc) * 32; \
        const __half* Bg = B + (size_t)bcol * ldB + (kc) * 32; \
        const uint32_t sa = sA0 + (s) * STAGE_B; \
        const uint32_t sb = sB0 + (s) * STAGE_B; \
        _Pragma("unroll") \
        for (int h = 0; h < 2; h++) { \
            const int r = l_r + h * 64; \
            cp16(sa + r * 80 + l_cc * 16, Ag + (size_t)r * ldA + l_cc * 8); \
            cp16(sb + r * 80 + l_cc * 16, Bg + (size_t)r * ldB + l_cc * 8); \
        } \
    } while (0)

    // prologue: stages 0..2
    LOAD_STAGE(0, 0); CP_COMMIT();
    if (nk > 1) LOAD_STAGE(1, 1);
    CP_COMMIT();
    if (nk > 2) LOAD_STAGE(2, 2);
    CP_COMMIT();

    for (int i = 0; i < nk; i++) {
        CP_WAIT(2);
        __syncthreads();
        if (i + 3 < nk) LOAD_STAGE((i + 3) & 3, i + 3);
        CP_COMMIT();

        const uint32_t sa = aAddr + (i & 3) * STAGE_B;
        const uint32_t sb = bAddr + (i & 3) * STAGE_B;
#pragma unroll
        for (int k16 = 0; k16 < 2; k16++) {
            uint32_t afr[4][4], bfr[4][2];
#pragma unroll
            for (int mi = 0; mi < 4; mi++)
                ldm_x4(afr[mi], sa + k16 * 32 + mi * (16 * 80));
            {
                uint32_t bt[4];
                ldm_x4(bt, sb + k16 * 32);
                bfr[0][0] = bt[0]; bfr[0][1] = bt[1];
                bfr[1][0] = bt[2]; bfr[1][1] = bt[3];
                ldm_x4(bt, sb + k16 * 32 + 16 * 80);
                bfr[2][0] = bt[0]; bfr[2][1] = bt[1];
                bfr[3][0] = bt[2]; bfr[3][1] = bt[3];
            }
#pragma unroll
            for (int mi = 0; mi < 4; mi++)
#pragma unroll
                for (int ni = 0; ni < 4; ni++)
                    mma16(acc[mi][ni], afr[mi], bfr[ni]);
        }
    }

    // ---------------- epilogue ----------------
    float colacc[4][2];
    if (MODE == 2) {
#pragma unroll
        for (int ni = 0; ni < 4; ni++) { colacc[ni][0] = 0.0f; colacc[ni][1] = 0.0f; }
        if (tid < 128) cs[tid] = 0.0f;
    }
    const float* suf = (MODE == 3) ? bias + ((size_t)z * (NBK + 1) + by + 1) * Hn : nullptr;

#pragma unroll
    for (int mi = 0; mi < 4; mi++) {
        const int r0 = brow + wm * 64 + mi * 16 + grp;
#pragma unroll
        for (int half = 0; half < 2; half++) {
            const int r = r0 + half * 8;
            float rbias = 0.0f;
            if (MODE == 1) rbias = __ldg(&bias[r]);
#pragma unroll
            for (int ni = 0; ni < 4; ni++) {
                const int c = bcol + wn * 32 + ni * 8 + 2 * tig;
                float v0 = acc[mi][ni][half * 2 + 0];
                float v1 = acc[mi][ni][half * 2 + 1];
                if (MODE == 0) {
                    v0 += __ldg(&bias[c]); v1 += __ldg(&bias[c + 1]);
                } else if (MODE == 1) {
                    v0 += rbias; v1 += rbias;
                } else if (MODE == 2) {
                    // E' = alpha * exp(score*s); masked-out entries are alpha*1
                    v0 = (r >= c)     ? __expf(fmaf(v0, ATTN_SCALE, LN_ALPHA)) : ALPHA;
                    v1 = (r >= c + 1) ? __expf(fmaf(v1, ATTN_SCALE, LN_ALPHA)) : ALPHA;
                }
                if (MODE == 3) {
                    float* Cf = (float*)Cv + (size_t)z * zC;
                    v0 = fmaf(v0, INV_BETA, __ldg(&suf[c]));
                    v1 = fmaf(v1, INV_BETA, __ldg(&suf[c + 1]));
                    *reinterpret_cast<float2*>(Cf + (size_t)r * ldC + c) = make_float2(v0, v1);
                } else {
                    __half2 hv = __floats2half2_rn(v0, v1);
                    if (MODE == 2) {
                        const float2 f = __half22float2(hv);
                        colacc[ni][0] += f.x; colacc[ni][1] += f.y;
                    }
                    __half* Ch = (__half*)Cv + (size_t)z * zC;
                    *reinterpret_cast<__half2*>(Ch + (size_t)r * ldC + c) = hv;
                }
            }
        }
    }

    if (MODE == 2) {
        __syncthreads();
#pragma unroll
        for (int ni = 0; ni < 4; ni++) {
            atomicAdd(&cs[wn * 32 + ni * 8 + 2 * tig],     colacc[ni][0]);
            atomicAdd(&cs[wn * 32 + ni * 8 + 2 * tig + 1], colacc[ni][1]);
        }
        __syncthreads();
        if (tid < 128) atomicAdd(&aux[(size_t)z * Tn + bcol + tid], cs[tid]);
    }
}

// ---------------- small kernels ---------------------------------------------
// transpose [R, Cc] f32 -> [Cc, R] fp16
__global__ void __launch_bounds__(256) transpose_h(
    const float* __restrict__ src, __half* __restrict__ dst, int R, int Cc)
{
    __shared__ float t[32][33];
    const int x = blockIdx.x * 32 + threadIdx.x;
    const int y0 = blockIdx.y * 32;
#pragma unroll
    for (int j = 0; j < 32; j += 8)
        t[threadIdx.y + j][threadIdx.x] = src[(size_t)(y0 + threadIdx.y + j) * Cc + x];
    __syncthreads();
    const int xo = y0 + threadIdx.x;
    const int yo0 = blockIdx.x * 32;
#pragma unroll
    for (int j = 0; j < 32; j += 8)
        dst[(size_t)(yo0 + threadIdx.y + j) * R + xo] = __float2half_rn(t[threadIdx.x][threadIdx.y + j]);
}

// f32 -> fp16 (4 elems/thread)
__global__ void __launch_bounds__(256) round_xh(const float* __restrict__ in, __half* __restrict__ o)
{
    const size_t i = (size_t)blockIdx.x * 256 + threadIdx.x;
    float4 v = reinterpret_cast<const float4*>(in)[i];
    uint2 w;
    w.x = h2_as_u32(__floats2half2_rn(v.x, v.y));
    w.y = h2_as_u32(__floats2half2_rn(v.z, v.w));
    reinterpret_cast<uint2*>(o)[i] = w;
}

// D'[b*Tn+k] = ALPHA * (k & ~127): analytic contribution of the all-ones rows
__global__ void __launch_bounds__(256) init_d(float* __restrict__ D)
{
    const int i = blockIdx.x * 256 + threadIdx.x;
    D[i] = ALPHA * (float)((i & (Tn - 1)) & ~127);
}

// vt2[h, b*T+t] = BETA * vt / D'[b*T+t]   (8 halfs/thread)
__global__ void __launch_bounds__(256) vtscale_h(__half* __restrict__ VT, const float* __restrict__ D)
{
    const size_t i8 = (size_t)blockIdx.x * 256 + threadIdx.x;
    uint4 raw = reinterpret_cast<uint4*>(VT)[i8];
    __half2* hp = reinterpret_cast<__half2*>(&raw);
    const int base = (int)((i8 * 8) & (BT - 1));
    const float4 d0 = *reinterpret_cast<const float4*>(D + base);
    const float4 d1 = *reinterpret_cast<const float4*>(D + base + 4);
    float2 f;
    f = __half22float2(hp[0]); hp[0] = __floats2half2_rn(BETA * f.x / d0.x, BETA * f.y / d0.y);
    f = __half22float2(hp[1]); hp[1] = __floats2half2_rn(BETA * f.x / d0.z, BETA * f.y / d0.w);
    f = __half22float2(hp[2]); hp[2] = __floats2half2_rn(BETA * f.x / d1.x, BETA * f.y / d1.y);
    f = __half22float2(hp[3]); hp[3] = __floats2half2_rn(BETA * f.x / d1.z, BETA * f.y / d1.w);
    reinterpret_cast<uint4*>(VT)[i8] = raw;
}

// Suf[z][bi][n] = ALPHA * sum_{k >= bi*128} v[n,k]/D'[k]  = (ALPHA/BETA)*sum vt2
__global__ void __launch_bounds__(128) suffix_v(const __half* __restrict__ VT, float* __restrict__ S)
{
    const int n = blockIdx.x, z = blockIdx.y;
    const int tid = threadIdx.x, wid = tid >> 5, lane = tid & 31;
    const __half* row = VT + (size_t)n * BT + (size_t)z * Tn;
    __shared__ float chunk[NBK];
#pragma unroll
    for (int g = 0; g < NBK / 4; g++) {
        const int bi = g * 4 + wid;
        float v = 0.0f;
#pragma unroll
        for (int j = 0; j < 4; j++) v += __half2float(row[bi * 128 + j * 32 + lane]);
#pragma unroll
        for (int o = 16; o; o >>= 1) v += __shfl_xor_sync(0xFFFFFFFFu, v, o);
        if (lane == 0) chunk[bi] = v;
    }
    __syncthreads();
    if (tid == 0) {
        float s = 0.0f;
        S[((size_t)z * (NBK + 1) + NBK) * Hn + n] = 0.0f;
        for (int bi = NBK - 1; bi >= 0; bi--) {
            s += chunk[bi];
            S[((size_t)z * (NBK + 1) + bi) * Hn + n] = s * SUF_SCALE;
        }
    }
}

// ---------------- host -------------------------------------------------------
extern "C" void kernel_launch(void* const* d_in, const int* in_sizes, int n_in,
                              void* d_out, int out_size)
{
    (void)in_sizes; (void)n_in; (void)out_size;
    const float* x  = (const float*)d_in[0];
    const float* Wq = (const float*)d_in[1];
    const float* bq = (const float*)d_in[2];
    const float* Wv = (const float*)d_in[3];
    const float* bv = (const float*)d_in[4];
    float* out = (float*)d_out;

    __half *q, *vt, *e, *xr, *wtq, *wtv;
    float *dI, *suf;
    cudaGetSymbolAddress((void**)&q,   g_q);
    cudaGetSymbolAddress((void**)&vt,  g_vt);
    cudaGetSymbolAddress((void**)&e,   g_e);
    cudaGetSymbolAddress((void**)&xr,  g_xr);
    cudaGetSymbolAddress((void**)&wtq, g_wtq);
    cudaGetSymbolAddress((void**)&wtv, g_wtv);
    cudaGetSymbolAddress((void**)&dI,  g_d);
    cudaGetSymbolAddress((void**)&suf, g_suf);

    cudaFuncSetAttribute(mm_h<0>, cudaFuncAttributeMaxDynamicSharedMemorySize, SMEM_BYTES);
    cudaFuncSetAttribute(mm_h<1>, cudaFuncAttributeMaxDynamicSharedMemorySize, SMEM_BYTES);
    cudaFuncSetAttribute(mm_h<2>, cudaFuncAttributeMaxDynamicSharedMemorySize, SMEM_BYTES);
    cudaFuncSetAttribute(mm_h<3>, cudaFuncAttributeMaxDynamicSharedMemorySize, SMEM_BYTES);

    // prep: transpose+convert weights, convert x, init denominators
    transpose_h<<<dim3(Hn / 32, En / 32), dim3(32, 8)>>>(Wq, wtq, En, Hn);
    transpose_h<<<dim3(Hn / 32, En / 32), dim3(32, 8)>>>(Wv, wtv, En, Hn);
    round_xh<<<(int)(((size_t)BT * En / 4) / 256), 256>>>(x, xr);
    init_d<<<BT / 256, 256>>>(dI);

    // q = x @ Wq + bq                    [B*T, H] fp16
    mm_h<0><<<dim3(Hn / 128, BT / 128, 1), 256, SMEM_BYTES>>>(
        xr, wtq, bq, q, nullptr, En, En, En, Hn, 0, 0, 0);
    // v^T = (x @ Wv + bv)^T              [H, B*T] fp16
    mm_h<1><<<dim3(BT / 128, Hn / 128, 1), 256, SMEM_BYTES>>>(
        wtv, xr, bv, vt, nullptr, En, En, En, BT, 0, 0, 0);
    // E' = alpha*exp(mask .* (q@q^T)*s), lower-tri blocks, fused column sums
    mm_h<2><<<dim3(NBK * (NBK + 1) / 2, 1, Bn), 256, SMEM_BYTES>>>(
        q, q, nullptr, e, dI, Hn, Hn, Hn, Tn,
        (long long)Tn * Hn, (long long)Tn * Hn, (long long)Tn * Tn);
    // fold BETA/D' into v^T columns, then alpha-scaled block-suffix sums
    vtscale_h<<<(int)(((size_t)Hn * BT / 8) / 256), 256>>>(vt, dI);
    suffix_v<<<dim3(Hn, Bn), 128>>>(vt, suf);
    // out = E'_tri @ vt2 / BETA + Suf[by+1]   per batch, triangular K-loop
    mm_h<3><<<dim3(Hn / 128, Tn / 128, Bn), 256, SMEM_BYTES>>>(
        e, vt, suf, out, nullptr, Tn, Tn, BT, Hn,
        (long long)Tn * Tn, (long long)Tn, (long long)Tn * Hn);
}

// round 15
// speedup vs baseline: 2.8653x; 1.0438x over previous
#include <cuda_runtime.h>
#include <cuda_fp16.h>
#include <math.h>
#include <stdint.h>

#define Bn 4
#define Tn 2048
#define En 1024
#define Hn 2048
#define BT (Bn*Tn)
#define NBK (Tn/128)               // 16 blocks along T
#define ATTN_SCALE 0.022097086912079612f
// E is stored scaled by ALPHA = 2^-18 to fit fp16; alpha cancels in E*v/D.
#define ALPHA     3.814697265625e-6f
#define LN_ALPHA (-12.476649250079015f)
// vt2 = BETA * v / D' to keep it in fp16 normal range
#define BETA      32.0f
#define INV_BETA  0.03125f
#define SUF_SCALE (ALPHA / BETA)

// ---------------- scratch (static device memory; no cudaMalloc) -------------
__device__ __half g_q  [(size_t)BT * Hn];   // q (fp16)                 32MB
__device__ __half g_vt [(size_t)Hn * BT];   // v^T/D' as [H, B*T]       32MB
__device__ __half g_e  [(size_t)BT * Tn];   // alpha * exp'd scores     32MB
__device__ __half g_xr [(size_t)BT * En];   // x rounded to fp16        16MB
__device__ __half g_wtq[(size_t)Hn * En];   // Wq^T fp16                 4MB
__device__ __half g_wtv[(size_t)Hn * En];   // Wv^T fp16                 4MB
__device__ float  g_d  [BT];                // scaled softmax denominators D'
__device__ float  g_suf[(size_t)Bn * (NBK + 1) * Hn];  // suffix sums (alpha-scaled)

// ---------------- helpers ----------------------------------------------------
__device__ __forceinline__ uint32_t smem_u32(const void* p) {
    uint32_t a;
    asm("{ .reg .u64 t; cvta.to.shared.u64 t, %1; cvt.u32.u64 %0, t; }" : "=r"(a) : "l"(p));
    return a;
}
__device__ __forceinline__ uint32_t h2_as_u32(__half2 h) {
    return *reinterpret_cast<uint32_t*>(&h);
}
__device__ __forceinline__ void cp16(uint32_t s, const void* g) {
    asm volatile("cp.async.ca.shared.global [%0], [%1], 16;" :: "r"(s), "l"(g));
}
#define CP_COMMIT() asm volatile("cp.async.commit_group;" ::: "memory")
#define CP_WAIT(n)  asm volatile("cp.async.wait_group %0;" :: "n"(n) : "memory")

__device__ __forceinline__ void ldm_x4(uint32_t* r, uint32_t addr) {
    asm volatile("ldmatrix.sync.aligned.m8n8.x4.shared.b16 {%0,%1,%2,%3}, [%4];"
        : "=r"(r[0]), "=r"(r[1]), "=r"(r[2]), "=r"(r[3]) : "r"(addr));
}
__device__ __forceinline__ void mma16(float* d, const uint32_t* a, const uint32_t* b) {
    asm volatile(
        "mma.sync.aligned.m16n8k16.row.col.f32.f16.f16.f32 "
        "{%0,%1,%2,%3}, {%4,%5,%6,%7}, {%8,%9}, {%0,%1,%2,%3};"
        : "+f"(d[0]), "+f"(d[1]), "+f"(d[2]), "+f"(d[3])
        : "r"(a[0]), "r"(a[1]), "r"(a[2]), "r"(a[3]), "r"(b[0]), "r"(b[1]));
}

// ---------------- fp16 tensor-core GEMM (NT: A[M,K] x B[N,K] -> C[M,N]) ------
// MODE 0: C(h) = h(acc + bias[col])                     (q projection)
// MODE 1: C(h) = h((acc + bias[row]) * BETA / D'[col])  (v^T proj, scale fused)
// MODE 2: C(h) = h(r>=c ? a*exp(acc*s) : a), tri launch, fused column sums
// MODE 3: C(f) = acc/BETA + Suf[by+1][col], triangular K-loop, heavy-first
#define SROW 40                     // halfs per smem row (80B, conflict-free)
#define STAGE_H (128 * SROW)        // 5120 halfs per operand stage
#define STAGE_B (STAGE_H * 2)       // 10240 bytes
#define NST 4
#define SMEM_BYTES (2 * NST * STAGE_B + 512)

template <int MODE>
__global__ void __launch_bounds__(256, 2) mm_h(
    const __half* __restrict__ A, const __half* __restrict__ B,
    const float* __restrict__ bias, void* __restrict__ Cv,
    float* __restrict__ aux,
    int K, int ldA, int ldB, int ldC,
    long long zA, long long zB, long long zC)
{
    extern __shared__ __half smh[];
    const int z = blockIdx.z;
    A += z * zA; B += z * zB;

    // block coordinates
    int by, bx;
    if (MODE == 2) {
        const int idx = blockIdx.x;
        by = (int)((sqrtf(8.0f * idx + 1.0f) - 1.0f) * 0.5f);
        while ((by + 1) * (by + 2) / 2 <= idx) ++by;
        while (by * (by + 1) / 2 > idx) --by;
        bx = idx - by * (by + 1) / 2;
    } else if (MODE == 3) {
        by = (gridDim.y - 1) - blockIdx.y;   // heavy blocks dispatch first
        bx = blockIdx.x;
    } else {
        by = blockIdx.y; bx = blockIdx.x;
    }
    const int brow = by * 128, bcol = bx * 128;
    const int nk = (MODE == 3) ? 4 * (by + 1) : (K >> 5);

    __half* As = smh;
    __half* Bs = smh + NST * STAGE_H;
    float*  cs = (float*)(smh + 2 * NST * STAGE_H);   // 128-col sums (MODE 2)

    const int tid = threadIdx.x, wid = tid >> 5, lane = tid & 31;
    const int wm = wid & 1, wn = wid >> 1;            // warp tile 64x32
    const int grp = lane >> 2, tig = lane & 3;

    // tile loader: 128 rows x 32 halfs; 16B chunks; thread -> (row, chunk) x2
    const int l_r = tid >> 2, l_cc = tid & 3;

    float acc[4][4][4];
#pragma unroll
    for (int i = 0; i < 4; i++)
#pragma unroll
        for (int j = 0; j < 4; j++)
#pragma unroll
            for (int k = 0; k < 4; k++) acc[i][j][k] = 0.0f;

    const uint32_t sA0 = smem_u32(As), sB0 = smem_u32(Bs);

    // ldmatrix lane-base addresses (bytes); 80B row stride is phase-conflict-free
    const uint32_t aAddr = sA0 + (wm * 64 + (lane & 15)) * 80 + ((lane >> 4) << 4);
    const uint32_t bAddr = sB0 + (wn * 32 + ((lane >> 4) << 3) + (lane & 7)) * 80
                         + (((lane >> 3) & 1) << 4);

#define LOAD_STAGE(s, kc) do { \
        const __half* Ag = A + (size_t)brow * ldA + (kc) * 32; \
        const __half* Bg = B + (size_t)bcol * ldB + (kc) * 32; \
        const uint32_t sa = sA0 + (s) * STAGE_B; \
        const uint32_t sb = sB0 + (s) * STAGE_B; \
        _Pragma("unroll") \
        for (int h = 0; h < 2; h++) { \
            const int r = l_r + h * 64; \
            cp16(sa + r * 80 + l_cc * 16, Ag + (size_t)r * ldA + l_cc * 8); \
            cp16(sb + r * 80 + l_cc * 16, Bg + (size_t)r * ldB + l_cc * 8); \
        } \
    } while (0)

    // prologue: stages 0..2
    LOAD_STAGE(0, 0); CP_COMMIT();
    if (nk > 1) LOAD_STAGE(1, 1);
    CP_COMMIT();
    if (nk > 2) LOAD_STAGE(2, 2);
    CP_COMMIT();

    for (int i = 0; i < nk; i++) {
        CP_WAIT(2);
        __syncthreads();
        if (i + 3 < nk) LOAD_STAGE((i + 3) & 3, i + 3);
        CP_COMMIT();

        const uint32_t sa = aAddr + (i & 3) * STAGE_B;
        const uint32_t sb = bAddr + (i & 3) * STAGE_B;
#pragma unroll
        for (int k16 = 0; k16 < 2; k16++) {
            uint32_t afr[4][4], bfr[4][2];
#pragma unroll
            for (int mi = 0; mi < 4; mi++)
                ldm_x4(afr[mi], sa + k16 * 32 + mi * (16 * 80));
            {
                uint32_t bt[4];
                ldm_x4(bt, sb + k16 * 32);
                bfr[0][0] = bt[0]; bfr[0][1] = bt[1];
                bfr[1][0] = bt[2]; bfr[1][1] = bt[3];
                ldm_x4(bt, sb + k16 * 32 + 16 * 80);
                bfr[2][0] = bt[0]; bfr[2][1] = bt[1];
                bfr[3][0] = bt[2]; bfr[3][1] = bt[3];
            }
#pragma unroll
            for (int mi = 0; mi < 4; mi++)
#pragma unroll
                for (int ni = 0; ni < 4; ni++)
                    mma16(acc[mi][ni], afr[mi], bfr[ni]);
        }
    }

    // ---------------- epilogue ----------------
    float colacc[4][2];
    if (MODE == 2) {
#pragma unroll
        for (int ni = 0; ni < 4; ni++) { colacc[ni][0] = 0.0f; colacc[ni][1] = 0.0f; }
        if (tid < 128) cs[tid] = 0.0f;
    }
    const float* suf = (MODE == 3) ? bias + ((size_t)z * (NBK + 1) + by + 1) * Hn : nullptr;

#pragma unroll
    for (int mi = 0; mi < 4; mi++) {
        const int r0 = brow + wm * 64 + mi * 16 + grp;
#pragma unroll
        for (int half = 0; half < 2; half++) {
            const int r = r0 + half * 8;
            float rbias = 0.0f;
            if (MODE == 1) rbias = __ldg(&bias[r]);
#pragma unroll
            for (int ni = 0; ni < 4; ni++) {
                const int c = bcol + wn * 32 + ni * 8 + 2 * tig;
                float v0 = acc[mi][ni][half * 2 + 0];
                float v1 = acc[mi][ni][half * 2 + 1];
                if (MODE == 0) {
                    v0 += __ldg(&bias[c]); v1 += __ldg(&bias[c + 1]);
                } else if (MODE == 1) {
                    // fused: vt2 = BETA * (v + bias) / D'[col]
                    v0 = BETA * (v0 + rbias) / __ldg(&aux[c]);
                    v1 = BETA * (v1 + rbias) / __ldg(&aux[c + 1]);
                } else if (MODE == 2) {
                    // E' = alpha * exp(score*s); masked-out entries are alpha*1
                    v0 = (r >= c)     ? __expf(fmaf(v0, ATTN_SCALE, LN_ALPHA)) : ALPHA;
                    v1 = (r >= c + 1) ? __expf(fmaf(v1, ATTN_SCALE, LN_ALPHA)) : ALPHA;
                }
                if (MODE == 3) {
                    float* Cf = (float*)Cv + (size_t)z * zC;
                    v0 = fmaf(v0, INV_BETA, __ldg(&suf[c]));
                    v1 = fmaf(v1, INV_BETA, __ldg(&suf[c + 1]));
                    *reinterpret_cast<float2*>(Cf + (size_t)r * ldC + c) = make_float2(v0, v1);
                } else {
                    __half2 hv = __floats2half2_rn(v0, v1);
                    if (MODE == 2) {
                        const float2 f = __half22float2(hv);
                        colacc[ni][0] += f.x; colacc[ni][1] += f.y;
                    }
                    __half* Ch = (__half*)Cv + (size_t)z * zC;
                    *reinterpret_cast<__half2*>(Ch + (size_t)r * ldC + c) = hv;
                }
            }
        }
    }

    if (MODE == 2) {
        __syncthreads();
#pragma unroll
        for (int ni = 0; ni < 4; ni++) {
            atomicAdd(&cs[wn * 32 + ni * 8 + 2 * tig],     colacc[ni][0]);
            atomicAdd(&cs[wn * 32 + ni * 8 + 2 * tig + 1], colacc[ni][1]);
        }
        __syncthreads();
        if (tid < 128) atomicAdd(&aux[(size_t)z * Tn + bcol + tid], cs[tid]);
    }
}

// ---------------- small kernels ---------------------------------------------
// transpose [R, Cc] f32 -> [Cc, R] fp16
__global__ void __launch_bounds__(256) transpose_h(
    const float* __restrict__ src, __half* __restrict__ dst, int R, int Cc)
{
    __shared__ float t[32][33];
    const int x = blockIdx.x * 32 + threadIdx.x;
    const int y0 = blockIdx.y * 32;
#pragma unroll
    for (int j = 0; j < 32; j += 8)
        t[threadIdx.y + j][threadIdx.x] = src[(size_t)(y0 + threadIdx.y + j) * Cc + x];
    __syncthreads();
    const int xo = y0 + threadIdx.x;
    const int yo0 = blockIdx.x * 32;
#pragma unroll
    for (int j = 0; j < 32; j += 8)
        dst[(size_t)(yo0 + threadIdx.y + j) * R + xo] = __float2half_rn(t[threadIdx.x][threadIdx.y + j]);
}

// f32 -> fp16 (4 elems/thread)
__global__ void __launch_bounds__(256) round_xh(const float* __restrict__ in, __half* __restrict__ o)
{
    const size_t i = (size_t)blockIdx.x * 256 + threadIdx.x;
    float4 v = reinterpret_cast<const float4*>(in)[i];
    uint2 w;
    w.x = h2_as_u32(__floats2half2_rn(v.x, v.y));
    w.y = h2_as_u32(__floats2half2_rn(v.z, v.w));
    reinterpret_cast<uint2*>(o)[i] = w;
}

// D'[b*Tn+k] = ALPHA * (k & ~127): analytic contribution of the all-ones rows
__global__ void __launch_bounds__(256) init_d(float* __restrict__ D)
{
    const int i = blockIdx.x * 256 + threadIdx.x;
    D[i] = ALPHA * (float)((i & (Tn - 1)) & ~127);
}

// Suf[z][bi][n] = ALPHA * sum_{k >= bi*128} v[n,k]/D'[k]  = (ALPHA/BETA)*sum vt2
__global__ void __launch_bounds__(128) suffix_v(const __half* __restrict__ VT, float* __restrict__ S)
{
    const int n = blockIdx.x, z = blockIdx.y;
    const int tid = threadIdx.x, wid = tid >> 5, lane = tid & 31;
    const __half* row = VT + (size_t)n * BT + (size_t)z * Tn;
    __shared__ float chunk[NBK];
#pragma unroll
    for (int g = 0; g < NBK / 4; g++) {
        const int bi = g * 4 + wid;
        float v = 0.0f;
#pragma unroll
        for (int j = 0; j < 4; j++) v += __half2float(row[bi * 128 + j * 32 + lane]);
#pragma unroll
        for (int o = 16; o; o >>= 1) v += __shfl_xor_sync(0xFFFFFFFFu, v, o);
        if (lane == 0) chunk[bi] = v;
    }
    __syncthreads();
    if (tid == 0) {
        float s = 0.0f;
        S[((size_t)z * (NBK + 1) + NBK) * Hn + n] = 0.0f;
        for (int bi = NBK - 1; bi >= 0; bi--) {
            s += chunk[bi];
            S[((size_t)z * (NBK + 1) + bi) * Hn + n] = s * SUF_SCALE;
        }
    }
}

// ---------------- host -------------------------------------------------------
extern "C" void kernel_launch(void* const* d_in, const int* in_sizes, int n_in,
                              void* d_out, int out_size)
{
    (void)in_sizes; (void)n_in; (void)out_size;
    const float* x  = (const float*)d_in[0];
    const float* Wq = (const float*)d_in[1];
    const float* bq = (const float*)d_in[2];
    const float* Wv = (const float*)d_in[3];
    const float* bv = (const float*)d_in[4];
    float* out = (float*)d_out;

    __half *q, *vt, *e, *xr, *wtq, *wtv;
    float *dI, *suf;
    cudaGetSymbolAddress((void**)&q,   g_q);
    cudaGetSymbolAddress((void**)&vt,  g_vt);
    cudaGetSymbolAddress((void**)&e,   g_e);
    cudaGetSymbolAddress((void**)&xr,  g_xr);
    cudaGetSymbolAddress((void**)&wtq, g_wtq);
    cudaGetSymbolAddress((void**)&wtv, g_wtv);
    cudaGetSymbolAddress((void**)&dI,  g_d);
    cudaGetSymbolAddress((void**)&suf, g_suf);

    cudaFuncSetAttribute(mm_h<0>, cudaFuncAttributeMaxDynamicSharedMemorySize, SMEM_BYTES);
    cudaFuncSetAttribute(mm_h<1>, cudaFuncAttributeMaxDynamicSharedMemorySize, SMEM_BYTES);
    cudaFuncSetAttribute(mm_h<2>, cudaFuncAttributeMaxDynamicSharedMemorySize, SMEM_BYTES);
    cudaFuncSetAttribute(mm_h<3>, cudaFuncAttributeMaxDynamicSharedMemorySize, SMEM_BYTES);

    // prep: transpose+convert weights, convert x, init denominators
    transpose_h<<<dim3(Hn / 32, En / 32), dim3(32, 8)>>>(Wq, wtq, En, Hn);
    transpose_h<<<dim3(Hn / 32, En / 32), dim3(32, 8)>>>(Wv, wtv, En, Hn);
    round_xh<<<(int)(((size_t)BT * En / 4) / 256), 256>>>(x, xr);
    init_d<<<BT / 256, 256>>>(dI);

    // q = x @ Wq + bq                    [B*T, H] fp16
    mm_h<0><<<dim3(Hn / 128, BT / 128, 1), 256, SMEM_BYTES>>>(
        xr, wtq, bq, q, nullptr, En, En, En, Hn, 0, 0, 0);
    // E' = alpha*exp(mask .* (q@q^T)*s), lower-tri blocks, fused column sums -> D'
    mm_h<2><<<dim3(NBK * (NBK + 1) / 2, 1, Bn), 256, SMEM_BYTES>>>(
        q, q, nullptr, e, dI, Hn, Hn, Hn, Tn,
        (long long)Tn * Hn, (long long)Tn * Hn, (long long)Tn * Tn);
    // vt2 = BETA*(x @ Wv + bv)^T / D'    [H, B*T] fp16, scaling fused in epilogue
    mm_h<1><<<dim3(BT / 128, Hn / 128, 1), 256, SMEM_BYTES>>>(
        wtv, xr, bv, vt, dI, En, En, En, BT, 0, 0, 0);
    // alpha-scaled block-suffix sums of vt2
    suffix_v<<<dim3(Hn, Bn), 128>>>(vt, suf);
    // out = E'_tri @ vt2 / BETA + Suf[by+1]   per batch, heavy blocks first
    mm_h<3><<<dim3(Hn / 128, Tn / 128, Bn), 256, SMEM_BYTES>>>(
        e, vt, suf, out, nullptr, Tn, Tn, BT, Hn,
        (long long)Tn * Tn, (long long)Tn, (long long)Tn * Hn);
}

// round 16
// speedup vs baseline: 3.2380x; 1.1300x over previous
#include <cuda_runtime.h>
#include <cuda_fp16.h>
#include <math.h>
#include <stdint.h>

#define Bn 4
#define Tn 2048
#define En 1024
#define Hn 2048
#define BT (Bn*Tn)
#define NBK (Tn/128)               // 16 blocks along T
#define ATTN_SCALE 0.022097086912079612f
// E is stored scaled by ALPHA = 2^-18 to fit fp16; alpha cancels in E*v/D.
#define ALPHA     3.814697265625e-6f
#define LN_ALPHA (-12.476649250079015f)
// vt2 = BETA * v / D' to keep it in fp16 normal range
#define BETA      32.0f
#define INV_BETA  0.03125f
#define SUF_SCALE (ALPHA / BETA)

// ---------------- scratch (static device memory; no cudaMalloc) -------------
// g_q is repurposed: [y : BT*En][M : En*En][wqh : En*Hn]  (11.5M of 16.7M halfs)
__device__ __half g_q  [(size_t)BT * Hn];
__device__ __half g_vt [(size_t)Hn * BT];   // v^T/D' as [H, B*T]       32MB
__device__ __half g_e  [(size_t)BT * Tn];   // alpha * exp'd scores     32MB
__device__ __half g_xr [(size_t)BT * En];   // x rounded to fp16        16MB
__device__ __half g_wtv[(size_t)Hn * En];   // Wv^T fp16                 4MB
__device__ float  g_d  [BT];                // scaled softmax denominators D'
__device__ float  g_suf[(size_t)Bn * (NBK + 1) * Hn];  // suffix sums (alpha-scaled)
__device__ float  g_w2 [En];                // Wq @ bq
__device__ float  g_c  [1];                 // |bq|^2
__device__ float  g_t  [BT];                // x @ (Wq bq) + 0.5*|bq|^2

// ---------------- helpers ----------------------------------------------------
__device__ __forceinline__ uint32_t smem_u32(const void* p) {
    uint32_t a;
    asm("{ .reg .u64 t; cvta.to.shared.u64 t, %1; cvt.u32.u64 %0, t; }" : "=r"(a) : "l"(p));
    return a;
}
__device__ __forceinline__ uint32_t h2_as_u32(__half2 h) {
    return *reinterpret_cast<uint32_t*>(&h);
}
__device__ __forceinline__ void cp16(uint32_t s, const void* g) {
    asm volatile("cp.async.ca.shared.global [%0], [%1], 16;" :: "r"(s), "l"(g));
}
#define CP_COMMIT() asm volatile("cp.async.commit_group;" ::: "memory")
#define CP_WAIT(n)  asm volatile("cp.async.wait_group %0;" :: "n"(n) : "memory")

__device__ __forceinline__ void ldm_x4(uint32_t* r, uint32_t addr) {
    asm volatile("ldmatrix.sync.aligned.m8n8.x4.shared.b16 {%0,%1,%2,%3}, [%4];"
        : "=r"(r[0]), "=r"(r[1]), "=r"(r[2]), "=r"(r[3]) : "r"(addr));
}
__device__ __forceinline__ void mma16(float* d, const uint32_t* a, const uint32_t* b) {
    asm volatile(
        "mma.sync.aligned.m16n8k16.row.col.f32.f16.f16.f32 "
        "{%0,%1,%2,%3}, {%4,%5,%6,%7}, {%8,%9}, {%0,%1,%2,%3};"
        : "+f"(d[0]), "+f"(d[1]), "+f"(d[2]), "+f"(d[3])
        : "r"(a[0]), "r"(a[1]), "r"(a[2]), "r"(a[3]), "r"(b[0]), "r"(b[1]));
}

// ---------------- fp16 tensor-core GEMM (NT: A[M,K] x B[N,K] -> C[M,N]) ------
// MODE 0: C(h) = h(acc + bias[col])                     (unused now)
// MODE 1: C(h) = h((acc + bias[row]) * BETA / D'[col])  (v^T proj, scale fused)
// MODE 2: C(h) = h(r>=c ? a*exp((acc+t[r]+t[c])*s) : a), tri launch, col sums
// MODE 3: C(f) = acc/BETA + Suf[by+1][col], triangular K-loop, heavy-first
// MODE 4: C(h) = h(acc)                                 (M and y GEMMs)
#define SROW 40                     // halfs per smem row (80B, conflict-free)
#define STAGE_H (128 * SROW)        // 5120 halfs per operand stage
#define STAGE_B (STAGE_H * 2)       // 10240 bytes
#define NST 4
#define SMEM_BYTES (2 * NST * STAGE_B + 512)

template <int MODE>
__global__ void __launch_bounds__(256, 2) mm_h(
    const __half* __restrict__ A, const __half* __restrict__ B,
    const float* __restrict__ bias, void* __restrict__ Cv,
    float* __restrict__ aux,
    int K, int ldA, int ldB, int ldC,
    long long zA, long long zB, long long zC)
{
    extern __shared__ __half smh[];
    const int z = blockIdx.z;
    A += z * zA; B += z * zB;

    // block coordinates
    int by, bx;
    if (MODE == 2) {
        const int idx = blockIdx.x;
        by = (int)((sqrtf(8.0f * idx + 1.0f) - 1.0f) * 0.5f);
        while ((by + 1) * (by + 2) / 2 <= idx) ++by;
        while (by * (by + 1) / 2 > idx) --by;
        bx = idx - by * (by + 1) / 2;
    } else if (MODE == 3) {
        by = (gridDim.y - 1) - blockIdx.y;   // heavy blocks dispatch first
        bx = blockIdx.x;
    } else {
        by = blockIdx.y; bx = blockIdx.x;
    }
    const int brow = by * 128, bcol = bx * 128;
    const int nk = (MODE == 3) ? 4 * (by + 1) : (K >> 5);

    __half* As = smh;
    __half* Bs = smh + NST * STAGE_H;
    float*  cs = (float*)(smh + 2 * NST * STAGE_H);   // 128-col sums (MODE 2)

    const int tid = threadIdx.x, wid = tid >> 5, lane = tid & 31;
    const int wm = wid & 1, wn = wid >> 1;            // warp tile 64x32
    const int grp = lane >> 2, tig = lane & 3;

    // tile loader: 128 rows x 32 halfs; 16B chunks; thread -> (row, chunk) x2
    const int l_r = tid >> 2, l_cc = tid & 3;

    float acc[4][4][4];
#pragma unroll
    for (int i = 0; i < 4; i++)
#pragma unroll
        for (int j = 0; j < 4; j++)
#pragma unroll
            for (int k = 0; k < 4; k++) acc[i][j][k] = 0.0f;

    const uint32_t sA0 = smem_u32(As), sB0 = smem_u32(Bs);

    // ldmatrix lane-base addresses (bytes); 80B row stride is phase-conflict-free
    const uint32_t aAddr = sA0 + (wm * 64 + (lane & 15)) * 80 + ((lane >> 4) << 4);
    const uint32_t bAddr = sB0 + (wn * 32 + ((lane >> 4) << 3) + (lane & 7)) * 80
                         + (((lane >> 3) & 1) << 4);

#define LOAD_STAGE(s, kc) do { \
        const __half* Ag = A + (size_t)brow * ldA + (kc) * 32; \
        const __half* Bg = B + (size_t)bcol * ldB + (kc) * 32; \
        const uint32_t sa = sA0 + (s) * STAGE_B; \
        const uint32_t sb = sB0 + (s) * STAGE_B; \
        _Pragma("unroll") \
        for (int h = 0; h < 2; h++) { \
            const int r = l_r + h * 64; \
            cp16(sa + r * 80 + l_cc * 16, Ag + (size_t)r * ldA + l_cc * 8); \
            cp16(sb + r * 80 + l_cc * 16, Bg + (size_t)r * ldB + l_cc * 8); \
        } \
    } while (0)

    // prologue: stages 0..2
    LOAD_STAGE(0, 0); CP_COMMIT();
    if (nk > 1) LOAD_STAGE(1, 1);
    CP_COMMIT();
    if (nk > 2) LOAD_STAGE(2, 2);
    CP_COMMIT();

    for (int i = 0; i < nk; i++) {
        CP_WAIT(2);
        __syncthreads();
        if (i + 3 < nk) LOAD_STAGE((i + 3) & 3, i + 3);
        CP_COMMIT();

        const uint32_t sa = aAddr + (i & 3) * STAGE_B;
        const uint32_t sb = bAddr + (i & 3) * STAGE_B;
#pragma unroll
        for (int k16 = 0; k16 < 2; k16++) {
            uint32_t afr[4][4], bfr[4][2];
#pragma unroll
            for (int mi = 0; mi < 4; mi++)
                ldm_x4(afr[mi], sa + k16 * 32 + mi * (16 * 80));
            {
                uint32_t bt[4];
                ldm_x4(bt, sb + k16 * 32);
                bfr[0][0] = bt[0]; bfr[0][1] = bt[1];
                bfr[1][0] = bt[2]; bfr[1][1] = bt[3];
                ldm_x4(bt, sb + k16 * 32 + 16 * 80);
                bfr[2][0] = bt[0]; bfr[2][1] = bt[1];
                bfr[3][0] = bt[2]; bfr[3][1] = bt[3];
            }
#pragma unroll
            for (int mi = 0; mi < 4; mi++)
#pragma unroll
                for (int ni = 0; ni < 4; ni++)
                    mma16(acc[mi][ni], afr[mi], bfr[ni]);
        }
    }

    // ---------------- epilogue ----------------
    float colacc[4][2];
    if (MODE == 2) {
#pragma unroll
        for (int ni = 0; ni < 4; ni++) { colacc[ni][0] = 0.0f; colacc[ni][1] = 0.0f; }
        if (tid < 128) cs[tid] = 0.0f;
    }
    const float* suf = (MODE == 3) ? bias + ((size_t)z * (NBK + 1) + by + 1) * Hn : nullptr;
    const float* tv  = (MODE == 2) ? bias + (size_t)z * Tn : nullptr;   // rank-1 bias

#pragma unroll
    for (int mi = 0; mi < 4; mi++) {
        const int r0 = brow + wm * 64 + mi * 16 + grp;
#pragma unroll
        for (int half = 0; half < 2; half++) {
            const int r = r0 + half * 8;
            float rbias = 0.0f;
            if (MODE == 1) rbias = __ldg(&bias[r]);
            if (MODE == 2) rbias = __ldg(&tv[r]);
#pragma unroll
            for (int ni = 0; ni < 4; ni++) {
                const int c = bcol + wn * 32 + ni * 8 + 2 * tig;
                float v0 = acc[mi][ni][half * 2 + 0];
                float v1 = acc[mi][ni][half * 2 + 1];
                if (MODE == 0) {
                    v0 += __ldg(&bias[c]); v1 += __ldg(&bias[c + 1]);
                } else if (MODE == 1) {
                    // fused: vt2 = BETA * (v + bias) / D'[col]
                    v0 = BETA * (v0 + rbias) / __ldg(&aux[c]);
                    v1 = BETA * (v1 + rbias) / __ldg(&aux[c + 1]);
                } else if (MODE == 2) {
                    // E' = alpha * exp((score + t[r] + t[c]) * s)
                    v0 = (r >= c)     ? __expf(fmaf(v0 + rbias + __ldg(&tv[c]),     ATTN_SCALE, LN_ALPHA)) : ALPHA;
                    v1 = (r >= c + 1) ? __expf(fmaf(v1 + rbias + __ldg(&tv[c + 1]), ATTN_SCALE, LN_ALPHA)) : ALPHA;
                }
                if (MODE == 3) {
                    float* Cf = (float*)Cv + (size_t)z * zC;
                    v0 = fmaf(v0, INV_BETA, __ldg(&suf[c]));
                    v1 = fmaf(v1, INV_BETA, __ldg(&suf[c + 1]));
                    *reinterpret_cast<float2*>(Cf + (size_t)r * ldC + c) = make_float2(v0, v1);
                } else {
                    __half2 hv = __floats2half2_rn(v0, v1);
                    if (MODE == 2) {
                        const float2 f = __half22float2(hv);
                        colacc[ni][0] += f.x; colacc[ni][1] += f.y;
                    }
                    __half* Ch = (__half*)Cv + (size_t)z * zC;
                    *reinterpret_cast<__half2*>(Ch + (size_t)r * ldC + c) = hv;
                }
            }
        }
    }

    if (MODE == 2) {
        __syncthreads();
#pragma unroll
        for (int ni = 0; ni < 4; ni++) {
            atomicAdd(&cs[wn * 32 + ni * 8 + 2 * tig],     colacc[ni][0]);
            atomicAdd(&cs[wn * 32 + ni * 8 + 2 * tig + 1], colacc[ni][1]);
        }
        __syncthreads();
        if (tid < 128) atomicAdd(&aux[(size_t)z * Tn + bcol + tid], cs[tid]);
    }
}

// ---------------- small kernels ---------------------------------------------
// transpose [R, Cc] f32 -> [Cc, R] fp16
__global__ void __launch_bounds__(256) transpose_h(
    const float* __restrict__ src, __half* __restrict__ dst, int R, int Cc)
{
    __shared__ float t[32][33];
    const int x = blockIdx.x * 32 + threadIdx.x;
    const int y0 = blockIdx.y * 32;
#pragma unroll
    for (int j = 0; j < 32; j += 8)
        t[threadIdx.y + j][threadIdx.x] = src[(size_t)(y0 + threadIdx.y + j) * Cc + x];
    __syncthreads();
    const int xo = y0 + threadIdx.x;
    const int yo0 = blockIdx.x * 32;
#pragma unroll
    for (int j = 0; j < 32; j += 8)
        dst[(size_t)(yo0 + threadIdx.y + j) * R + xo] = __float2half_rn(t[threadIdx.x][threadIdx.y + j]);
}

// f32 -> fp16 (4 elems/thread)
__global__ void __launch_bounds__(256) round_xh(const float* __restrict__ in, __half* __restrict__ o)
{
    const size_t i = (size_t)blockIdx.x * 256 + threadIdx.x;
    float4 v = reinterpret_cast<const float4*>(in)[i];
    uint2 w;
    w.x = h2_as_u32(__floats2half2_rn(v.x, v.y));
    w.y = h2_as_u32(__floats2half2_rn(v.z, v.w));
    reinterpret_cast<uint2*>(o)[i] = w;
}

// D'[b*Tn+k] = ALPHA * (k & ~127): analytic contribution of the all-ones rows
__global__ void __launch_bounds__(256) init_d(float* __restrict__ D)
{
    const int i = blockIdx.x * 256 + threadIdx.x;
    D[i] = ALPHA * (float)((i & (Tn - 1)) & ~127);
}

// w2[i] = Wq[i,:] . bq  (block per i); block En computes |bq|^2
__global__ void __launch_bounds__(256) prep_w2(
    const float* __restrict__ Wq, const float* __restrict__ bq,
    float* __restrict__ w2, float* __restrict__ cOut)
{
    __shared__ float red[8];
    const int tid = threadIdx.x, wid = tid >> 5, lane = tid & 31;
    float s = 0.0f;
    if (blockIdx.x < En) {
        const float* row = Wq + (size_t)blockIdx.x * Hn;
        for (int j = tid; j < Hn; j += 256) s += row[j] * bq[j];
    } else {
        for (int j = tid; j < Hn; j += 256) { const float b = bq[j]; s += b * b; }
    }
#pragma unroll
    for (int o = 16; o; o >>= 1) s += __shfl_xor_sync(0xFFFFFFFFu, s, o);
    if (lane == 0) red[wid] = s;
    __syncthreads();
    if (tid == 0) {
        float tot = 0.0f;
#pragma unroll
        for (int w = 0; w < 8; w++) tot += red[w];
        if (blockIdx.x < En) w2[blockIdx.x] = tot;
        else cOut[0] = tot;
    }
}

// t[r] = x[r,:] . w2 + 0.5*c    (warp per row)
__global__ void __launch_bounds__(256) prep_t(
    const float* __restrict__ x, const float* __restrict__ w2,
    const float* __restrict__ cptr, float* __restrict__ t)
{
    const int wid = threadIdx.x >> 5, lane = threadIdx.x & 31;
    const int r = blockIdx.x * 8 + wid;
    const float* row = x + (size_t)r * En;
    float s = 0.0f;
#pragma unroll
    for (int j = 0; j < En / 32; j++) s += row[lane + 32 * j] * w2[lane + 32 * j];
#pragma unroll
    for (int o = 16; o; o >>= 1) s += __shfl_xor_sync(0xFFFFFFFFu, s, o);
    if (lane == 0) t[r] = s + 0.5f * cptr[0];
}

// Suf[z][bi][n] = ALPHA * sum_{k >= bi*128} v[n,k]/D'[k]  = (ALPHA/BETA)*sum vt2
__global__ void __launch_bounds__(128) suffix_v(const __half* __restrict__ VT, float* __restrict__ S)
{
    const int n = blockIdx.x, z = blockIdx.y;
    const int tid = threadIdx.x, wid = tid >> 5, lane = tid & 31;
    const __half* row = VT + (size_t)n * BT + (size_t)z * Tn;
    __shared__ float chunk[NBK];
#pragma unroll
    for (int g = 0; g < NBK / 4; g++) {
        const int bi = g * 4 + wid;
        float v = 0.0f;
#pragma unroll
        for (int j = 0; j < 4; j++) v += __half2float(row[bi * 128 + j * 32 + lane]);
#pragma unroll
        for (int o = 16; o; o >>= 1) v += __shfl_xor_sync(0xFFFFFFFFu, v, o);
        if (lane == 0) chunk[bi] = v;
    }
    __syncthreads();
    if (tid == 0) {
        float s = 0.0f;
        S[((size_t)z * (NBK + 1) + NBK) * Hn + n] = 0.0f;
        for (int bi = NBK - 1; bi >= 0; bi--) {
            s += chunk[bi];
            S[((size_t)z * (NBK + 1) + bi) * Hn + n] = s * SUF_SCALE;
        }
    }
}

// ---------------- host -------------------------------------------------------
extern "C" void kernel_launch(void* const* d_in, const int* in_sizes, int n_in,
                              void* d_out, int out_size)
{
    (void)in_sizes; (void)n_in; (void)out_size;
    const float* x  = (const float*)d_in[0];
    const float* Wq = (const float*)d_in[1];
    const float* bq = (const float*)d_in[2];
    const float* Wv = (const float*)d_in[3];
    const float* bv = (const float*)d_in[4];
    float* out = (float*)d_out;

    __half *q, *vt, *e, *xr, *wtv;
    float *dI, *suf, *w2, *cS, *tV;
    cudaGetSymbolAddress((void**)&q,   g_q);
    cudaGetSymbolAddress((void**)&vt,  g_vt);
    cudaGetSymbolAddress((void**)&e,   g_e);
    cudaGetSymbolAddress((void**)&xr,  g_xr);
    cudaGetSymbolAddress((void**)&wtv, g_wtv);
    cudaGetSymbolAddress((void**)&dI,  g_d);
    cudaGetSymbolAddress((void**)&suf, g_suf);
    cudaGetSymbolAddress((void**)&w2,  g_w2);
    cudaGetSymbolAddress((void**)&cS,  g_c);
    cudaGetSymbolAddress((void**)&tV,  g_t);

    // carve y / M / Wq(fp16) out of the freed g_q region
    __half* y   = q;
    __half* Mh  = q + (size_t)BT * En;
    __half* wqh = q + (size_t)BT * En + (size_t)En * En;

    cudaFuncSetAttribute(mm_h<1>, cudaFuncAttributeMaxDynamicSharedMemorySize, SMEM_BYTES);
    cudaFuncSetAttribute(mm_h<2>, cudaFuncAttributeMaxDynamicSharedMemorySize, SMEM_BYTES);
    cudaFuncSetAttribute(mm_h<3>, cudaFuncAttributeMaxDynamicSharedMemorySize, SMEM_BYTES);
    cudaFuncSetAttribute(mm_h<4>, cudaFuncAttributeMaxDynamicSharedMemorySize, SMEM_BYTES);

    // prep: convert x and Wq, transpose Wv, init denominators, rank-1 bias terms
    round_xh<<<(int)(((size_t)BT * En / 4) / 256), 256>>>(x, xr);
    round_xh<<<(int)(((size_t)En * Hn / 4) / 256), 256>>>(Wq, wqh);
    transpose_h<<<dim3(Hn / 32, En / 32), dim3(32, 8)>>>(Wv, wtv, En, Hn);
    init_d<<<BT / 256, 256>>>(dI);
    prep_w2<<<En + 1, 256>>>(Wq, bq, w2, cS);
    prep_t<<<BT / 8, 256>>>(x, w2, cS, tV);

    // M = Wq @ Wq^T                 [En, En] fp16 (symmetric)
    mm_h<4><<<dim3(En / 128, En / 128, 1), 256, SMEM_BYTES>>>(
        wqh, wqh, nullptr, Mh, nullptr, Hn, Hn, Hn, En, 0, 0, 0);
    // y = x @ M                     [B*T, En] fp16  (M symmetric -> NT ok)
    mm_h<4><<<dim3(En / 128, BT / 128, 1), 256, SMEM_BYTES>>>(
        xr, Mh, nullptr, y, nullptr, En, En, En, En, 0, 0, 0);
    // E' = alpha*exp((y@x^T + t1' + 1t')*s), lower-tri blocks, fused col sums -> D'
    mm_h<2><<<dim3(NBK * (NBK + 1) / 2, 1, Bn), 256, SMEM_BYTES>>>(
        y, xr, tV, e, dI, En, En, En, Tn,
        (long long)Tn * En, (long long)Tn * En, (long long)Tn * Tn);
    // vt2 = BETA*(x @ Wv + bv)^T / D'    [H, B*T] fp16, scaling fused in epilogue
    mm_h<1><<<dim3(BT / 128, Hn / 128, 1), 256, SMEM_BYTES>>>(
        wtv, xr, bv, vt, dI, En, En, En, BT, 0, 0, 0);
    // alpha-scaled block-suffix sums of vt2
    suffix_v<<<dim3(Hn, Bn), 128>>>(vt, suf);
    // out = E'_tri @ vt2 / BETA + Suf[by+1]   per batch, heavy blocks first
    mm_h<3><<<dim3(Hn / 128, Tn / 128, Bn), 256, SMEM_BYTES>>>(
        e, vt, suf, out, nullptr, Tn, Tn, BT, Hn,
        (long long)Tn * Tn, (long long)Tn, (long long)Tn * Hn);
}

// round 17
// speedup vs baseline: 3.3168x; 1.0243x over previous
#include <cuda_runtime.h>
#include <cuda_fp16.h>
#include <math.h>
#include <stdint.h>

#define Bn 4
#define Tn 2048
#define En 1024
#define Hn 2048
#define BT (Bn*Tn)
#define NBK (Tn/128)               // 16 blocks along T
#define ATTN_SCALE 0.022097086912079612f
// E is stored scaled by ALPHA = 2^-18 to fit fp16; alpha cancels in E*v/D.
#define ALPHA     3.814697265625e-6f
#define LN_ALPHA (-12.476649250079015f)
// vt2 = BETA * v / D' to keep it in fp16 normal range
#define BETA      32.0f
#define INV_BETA  0.03125f
#define SUF_SCALE (ALPHA / BETA)

// ---------------- scratch (static device memory; no cudaMalloc) -------------
// g_q is repurposed: [y : BT*En][M : En*En][wqh : En*Hn]
__device__ __half g_q  [(size_t)BT * Hn];
__device__ __half g_vt [(size_t)Hn * BT];   // v^T/D' as [H, B*T]       32MB
__device__ __half g_e  [(size_t)BT * Tn];   // alpha * exp'd scores     32MB
__device__ __half g_xr [(size_t)BT * En];   // x rounded to fp16        16MB
__device__ __half g_wtv[(size_t)Hn * En];   // Wv^T fp16                 4MB
__device__ float  g_mf [(size_t)En * En];   // fp32 split-K partials of M
__device__ float  g_d  [BT];                // scaled softmax denominators D'
__device__ float  g_suf[(size_t)Bn * (NBK + 1) * Hn];  // suffix sums (alpha-scaled)
__device__ float  g_w2 [En];                // Wq @ bq
__device__ float  g_c  [1];                 // |bq|^2
__device__ float  g_t  [BT];                // x @ (Wq bq) + 0.5*|bq|^2

// ---------------- helpers ----------------------------------------------------
__device__ __forceinline__ uint32_t smem_u32(const void* p) {
    uint32_t a;
    asm("{ .reg .u64 t; cvta.to.shared.u64 t, %1; cvt.u32.u64 %0, t; }" : "=r"(a) : "l"(p));
    return a;
}
__device__ __forceinline__ uint32_t h2_as_u32(__half2 h) {
    return *reinterpret_cast<uint32_t*>(&h);
}
__device__ __forceinline__ void cp16(uint32_t s, const void* g) {
    asm volatile("cp.async.ca.shared.global [%0], [%1], 16;" :: "r"(s), "l"(g));
}
#define CP_COMMIT() asm volatile("cp.async.commit_group;" ::: "memory")
#define CP_WAIT(n)  asm volatile("cp.async.wait_group %0;" :: "n"(n) : "memory")

__device__ __forceinline__ void ldm_x4(uint32_t* r, uint32_t addr) {
    asm volatile("ldmatrix.sync.aligned.m8n8.x4.shared.b16 {%0,%1,%2,%3}, [%4];"
        : "=r"(r[0]), "=r"(r[1]), "=r"(r[2]), "=r"(r[3]) : "r"(addr));
}
__device__ __forceinline__ void mma16(float* d, const uint32_t* a, const uint32_t* b) {
    asm volatile(
        "mma.sync.aligned.m16n8k16.row.col.f32.f16.f16.f32 "
        "{%0,%1,%2,%3}, {%4,%5,%6,%7}, {%8,%9}, {%0,%1,%2,%3};"
        : "+f"(d[0]), "+f"(d[1]), "+f"(d[2]), "+f"(d[3])
        : "r"(a[0]), "r"(a[1]), "r"(a[2]), "r"(a[3]), "r"(b[0]), "r"(b[1]));
}

// ---------------- fp16 tensor-core GEMM (NT: A[M,K] x B[N,K] -> C[M,N]) ------
// MODE 1: C(h) = h((acc + bias[row]) * BETA / D'[col])  (v^T proj, scale fused)
// MODE 2: C(h) = h(r>=c ? a*exp((acc+t[r]+t[c])*s) : a), tri launch, col sums
// MODE 3: C(f) = acc/BETA + Suf[by+1][col], triangular K-loop, heavy-first
// MODE 4: C(h) = h(acc)                                 (y GEMM)
// MODE 5: atomicAdd(C(f), acc)                          (split-K M GEMM)
#define SROW 40                     // halfs per smem row (80B, conflict-free)
#define STAGE_H (128 * SROW)        // 5120 halfs per operand stage
#define STAGE_B (STAGE_H * 2)       // 10240 bytes
#define NST 4
#define SMEM_BYTES (2 * NST * STAGE_B + 512)

template <int MODE>
__global__ void __launch_bounds__(256, 2) mm_h(
    const __half* __restrict__ A, const __half* __restrict__ B,
    const float* __restrict__ bias, void* __restrict__ Cv,
    float* __restrict__ aux,
    int K, int ldA, int ldB, int ldC,
    long long zA, long long zB, long long zC)
{
    extern __shared__ __half smh[];
    const int z = blockIdx.z;
    A += z * zA; B += z * zB;

    // block coordinates
    int by, bx;
    if (MODE == 2) {
        const int idx = blockIdx.x;
        by = (int)((sqrtf(8.0f * idx + 1.0f) - 1.0f) * 0.5f);
        while ((by + 1) * (by + 2) / 2 <= idx) ++by;
        while (by * (by + 1) / 2 > idx) --by;
        bx = idx - by * (by + 1) / 2;
    } else if (MODE == 3) {
        by = (gridDim.y - 1) - blockIdx.y;   // heavy blocks dispatch first
        bx = blockIdx.x;
    } else {
        by = blockIdx.y; bx = blockIdx.x;
    }
    const int brow = by * 128, bcol = bx * 128;
    const int nk = (MODE == 3) ? 4 * (by + 1) : (K >> 5);

    __half* As = smh;
    __half* Bs = smh + NST * STAGE_H;
    float*  cs = (float*)(smh + 2 * NST * STAGE_H);   // 128-col sums (MODE 2)

    const int tid = threadIdx.x, wid = tid >> 5, lane = tid & 31;
    const int wm = wid & 1, wn = wid >> 1;            // warp tile 64x32
    const int grp = lane >> 2, tig = lane & 3;

    // tile loader: 128 rows x 32 halfs; 16B chunks; thread -> (row, chunk) x2
    const int l_r = tid >> 2, l_cc = tid & 3;

    float acc[4][4][4];
#pragma unroll
    for (int i = 0; i < 4; i++)
#pragma unroll
        for (int j = 0; j < 4; j++)
#pragma unroll
            for (int k = 0; k < 4; k++) acc[i][j][k] = 0.0f;

    const uint32_t sA0 = smem_u32(As), sB0 = smem_u32(Bs);

    // ldmatrix lane-base addresses (bytes); 80B row stride is phase-conflict-free
    const uint32_t aAddr = sA0 + (wm * 64 + (lane & 15)) * 80 + ((lane >> 4) << 4);
    const uint32_t bAddr = sB0 + (wn * 32 + ((lane >> 4) << 3) + (lane & 7)) * 80
                         + (((lane >> 3) & 1) << 4);

#define LOAD_STAGE(s, kc) do { \
        const __half* Ag = A + (size_t)brow * ldA + (kc) * 32; \
        const __half* Bg = B + (size_t)bcol * ldB + (kc) * 32; \
        const uint32_t sa = sA0 + (s) * STAGE_B; \
        const uint32_t sb = sB0 + (s) * STAGE_B; \
        _Pragma("unroll") \
        for (int h = 0; h < 2; h++) { \
            const int r = l_r + h * 64; \
            cp16(sa + r * 80 + l_cc * 16, Ag + (size_t)r * ldA + l_cc * 8); \
            cp16(sb + r * 80 + l_cc * 16, Bg + (size_t)r * ldB + l_cc * 8); \
        } \
    } while (0)

    // prologue: stages 0..2
    LOAD_STAGE(0, 0); CP_COMMIT();
    if (nk > 1) LOAD_STAGE(1, 1);
    CP_COMMIT();
    if (nk > 2) LOAD_STAGE(2, 2);
    CP_COMMIT();

    for (int i = 0; i < nk; i++) {
        CP_WAIT(2);
        __syncthreads();
        if (i + 3 < nk) LOAD_STAGE((i + 3) & 3, i + 3);
        CP_COMMIT();

        const uint32_t sa = aAddr + (i & 3) * STAGE_B;
        const uint32_t sb = bAddr + (i & 3) * STAGE_B;
#pragma unroll
        for (int k16 = 0; k16 < 2; k16++) {
            uint32_t afr[4][4], bfr[4][2];
#pragma unroll
            for (int mi = 0; mi < 4; mi++)
                ldm_x4(afr[mi], sa + k16 * 32 + mi * (16 * 80));
            {
                uint32_t bt[4];
                ldm_x4(bt, sb + k16 * 32);
                bfr[0][0] = bt[0]; bfr[0][1] = bt[1];
                bfr[1][0] = bt[2]; bfr[1][1] = bt[3];
                ldm_x4(bt, sb + k16 * 32 + 16 * 80);
                bfr[2][0] = bt[0]; bfr[2][1] = bt[1];
                bfr[3][0] = bt[2]; bfr[3][1] = bt[3];
            }
#pragma unroll
            for (int mi = 0; mi < 4; mi++)
#pragma unroll
                for (int ni = 0; ni < 4; ni++)
                    mma16(acc[mi][ni], afr[mi], bfr[ni]);
        }
    }

    // ---------------- epilogue ----------------
    float colacc[4][2];
    if (MODE == 2) {
#pragma unroll
        for (int ni = 0; ni < 4; ni++) { colacc[ni][0] = 0.0f; colacc[ni][1] = 0.0f; }
        if (tid < 128) cs[tid] = 0.0f;
    }
    const float* suf = (MODE == 3) ? bias + ((size_t)z * (NBK + 1) + by + 1) * Hn : nullptr;
    const float* tv  = (MODE == 2) ? bias + (size_t)z * Tn : nullptr;   // rank-1 bias

#pragma unroll
    for (int mi = 0; mi < 4; mi++) {
        const int r0 = brow + wm * 64 + mi * 16 + grp;
#pragma unroll
        for (int half = 0; half < 2; half++) {
            const int r = r0 + half * 8;
            float rbias = 0.0f;
            if (MODE == 1) rbias = __ldg(&bias[r]);
            if (MODE == 2) rbias = __ldg(&tv[r]);
#pragma unroll
            for (int ni = 0; ni < 4; ni++) {
                const int c = bcol + wn * 32 + ni * 8 + 2 * tig;
                float v0 = acc[mi][ni][half * 2 + 0];
                float v1 = acc[mi][ni][half * 2 + 1];
                if (MODE == 1) {
                    // fused: vt2 = BETA * (v + bias) / D'[col]
                    v0 = BETA * (v0 + rbias) / __ldg(&aux[c]);
                    v1 = BETA * (v1 + rbias) / __ldg(&aux[c + 1]);
                } else if (MODE == 2) {
                    // E' = alpha * exp((score + t[r] + t[c]) * s)
                    v0 = (r >= c)     ? __expf(fmaf(v0 + rbias + __ldg(&tv[c]),     ATTN_SCALE, LN_ALPHA)) : ALPHA;
                    v1 = (r >= c + 1) ? __expf(fmaf(v1 + rbias + __ldg(&tv[c + 1]), ATTN_SCALE, LN_ALPHA)) : ALPHA;
                }
                if (MODE == 3) {
                    float* Cf = (float*)Cv + (size_t)z * zC;
                    v0 = fmaf(v0, INV_BETA, __ldg(&suf[c]));
                    v1 = fmaf(v1, INV_BETA, __ldg(&suf[c + 1]));
                    *reinterpret_cast<float2*>(Cf + (size_t)r * ldC + c) = make_float2(v0, v1);
                } else if (MODE == 5) {
                    float* Cf = (float*)Cv;
                    atomicAdd(&Cf[(size_t)r * ldC + c],     v0);
                    atomicAdd(&Cf[(size_t)r * ldC + c + 1], v1);
                } else {
                    __half2 hv = __floats2half2_rn(v0, v1);
                    if (MODE == 2) {
                        const float2 f = __half22float2(hv);
                        colacc[ni][0] += f.x; colacc[ni][1] += f.y;
                    }
                    __half* Ch = (__half*)Cv + (size_t)z * zC;
                    *reinterpret_cast<__half2*>(Ch + (size_t)r * ldC + c) = hv;
                }
            }
        }
    }

    if (MODE == 2) {
        __syncthreads();
#pragma unroll
        for (int ni = 0; ni < 4; ni++) {
            atomicAdd(&cs[wn * 32 + ni * 8 + 2 * tig],     colacc[ni][0]);
            atomicAdd(&cs[wn * 32 + ni * 8 + 2 * tig + 1], colacc[ni][1]);
        }
        __syncthreads();
        if (tid < 128) atomicAdd(&aux[(size_t)z * Tn + bcol + tid], cs[tid]);
    }
}

// ---------------- small kernels ---------------------------------------------
// transpose [R, Cc] f32 -> [Cc, R] fp16
__global__ void __launch_bounds__(256) transpose_h(
    const float* __restrict__ src, __half* __restrict__ dst, int R, int Cc)
{
    __shared__ float t[32][33];
    const int x = blockIdx.x * 32 + threadIdx.x;
    const int y0 = blockIdx.y * 32;
#pragma unroll
    for (int j = 0; j < 32; j += 8)
        t[threadIdx.y + j][threadIdx.x] = src[(size_t)(y0 + threadIdx.y + j) * Cc + x];
    __syncthreads();
    const int xo = y0 + threadIdx.x;
    const int yo0 = blockIdx.x * 32;
#pragma unroll
    for (int j = 0; j < 32; j += 8)
        dst[(size_t)(yo0 + threadIdx.y + j) * R + xo] = __float2half_rn(t[threadIdx.x][threadIdx.y + j]);
}

// f32 -> fp16 (4 elems/thread)
__global__ void __launch_bounds__(256) round_xh(const float* __restrict__ in, __half* __restrict__ o)
{
    const size_t i = (size_t)blockIdx.x * 256 + threadIdx.x;
    float4 v = reinterpret_cast<const float4*>(in)[i];
    uint2 w;
    w.x = h2_as_u32(__floats2half2_rn(v.x, v.y));
    w.y = h2_as_u32(__floats2half2_rn(v.z, v.w));
    reinterpret_cast<uint2*>(o)[i] = w;
}

// w2[i] = Wq[i,:] . bq  (block per i); block En computes |bq|^2
__global__ void __launch_bounds__(256) prep_w2(
    const float* __restrict__ Wq, const float* __restrict__ bq,
    float* __restrict__ w2, float* __restrict__ cOut)
{
    __shared__ float red[8];
    const int tid = threadIdx.x, wid = tid >> 5, lane = tid & 31;
    float s = 0.0f;
    if (blockIdx.x < En) {
        const float* row = Wq + (size_t)blockIdx.x * Hn;
        for (int j = tid; j < Hn; j += 256) s += row[j] * bq[j];
    } else {
        for (int j = tid; j < Hn; j += 256) { const float b = bq[j]; s += b * b; }
    }
#pragma unroll
    for (int o = 16; o; o >>= 1) s += __shfl_xor_sync(0xFFFFFFFFu, s, o);
    if (lane == 0) red[wid] = s;
    __syncthreads();
    if (tid == 0) {
        float tot = 0.0f;
#pragma unroll
        for (int w = 0; w < 8; w++) tot += red[w];
        if (blockIdx.x < En) w2[blockIdx.x] = tot;
        else cOut[0] = tot;
    }
}

// t[r] = x[r,:] . w2 + 0.5*c; also initializes D'[r] (analytic all-ones part)
__global__ void __launch_bounds__(256) prep_t(
    const float* __restrict__ x, const float* __restrict__ w2,
    const float* __restrict__ cptr, float* __restrict__ t, float* __restrict__ D)
{
    const int wid = threadIdx.x >> 5, lane = threadIdx.x & 31;
    const int r = blockIdx.x * 8 + wid;
    const float* row = x + (size_t)r * En;
    float s = 0.0f;
#pragma unroll
    for (int j = 0; j < En / 32; j++) s += row[lane + 32 * j] * w2[lane + 32 * j];
#pragma unroll
    for (int o = 16; o; o >>= 1) s += __shfl_xor_sync(0xFFFFFFFFu, s, o);
    if (lane == 0) {
        t[r] = s + 0.5f * cptr[0];
        D[r] = ALPHA * (float)((r & (Tn - 1)) & ~127);
    }
}

// Suf[z][bi][n] = ALPHA * sum_{k >= bi*128} v[n,k]/D'[k]  = (ALPHA/BETA)*sum vt2
__global__ void __launch_bounds__(128) suffix_v(const __half* __restrict__ VT, float* __restrict__ S)
{
    const int n = blockIdx.x, z = blockIdx.y;
    const int tid = threadIdx.x, wid = tid >> 5, lane = tid & 31;
    const __half* row = VT + (size_t)n * BT + (size_t)z * Tn;
    __shared__ float chunk[NBK];
#pragma unroll
    for (int g = 0; g < NBK / 4; g++) {
        const int bi = g * 4 + wid;
        float v = 0.0f;
#pragma unroll
        for (int j = 0; j < 4; j++) v += __half2float(row[bi * 128 + j * 32 + lane]);
#pragma unroll
        for (int o = 16; o; o >>= 1) v += __shfl_xor_sync(0xFFFFFFFFu, v, o);
        if (lane == 0) chunk[bi] = v;
    }
    __syncthreads();
    if (tid == 0) {
        float s = 0.0f;
        S[((size_t)z * (NBK + 1) + NBK) * Hn + n] = 0.0f;
        for (int bi = NBK - 1; bi >= 0; bi--) {
            s += chunk[bi];
            S[((size_t)z * (NBK + 1) + bi) * Hn + n] = s * SUF_SCALE;
        }
    }
}

// ---------------- host -------------------------------------------------------
extern "C" void kernel_launch(void* const* d_in, const int* in_sizes, int n_in,
                              void* d_out, int out_size)
{
    (void)in_sizes; (void)n_in; (void)out_size;
    const float* x  = (const float*)d_in[0];
    const float* Wq = (const float*)d_in[1];
    const float* bq = (const float*)d_in[2];
    const float* Wv = (const float*)d_in[3];
    const float* bv = (const float*)d_in[4];
    float* out = (float*)d_out;

    __half *q, *vt, *e, *xr, *wtv;
    float *dI, *suf, *w2, *cS, *tV, *mf;
    cudaGetSymbolAddress((void**)&q,   g_q);
    cudaGetSymbolAddress((void**)&vt,  g_vt);
    cudaGetSymbolAddress((void**)&e,   g_e);
    cudaGetSymbolAddress((void**)&xr,  g_xr);
    cudaGetSymbolAddress((void**)&wtv, g_wtv);
    cudaGetSymbolAddress((void**)&dI,  g_d);
    cudaGetSymbolAddress((void**)&suf, g_suf);
    cudaGetSymbolAddress((void**)&w2,  g_w2);
    cudaGetSymbolAddress((void**)&cS,  g_c);
    cudaGetSymbolAddress((void**)&tV,  g_t);
    cudaGetSymbolAddress((void**)&mf,  g_mf);

    // carve y / M / Wq(fp16) out of the freed g_q region
    __half* y   = q;
    __half* Mh  = q + (size_t)BT * En;
    __half* wqh = q + (size_t)BT * En + (size_t)En * En;

    cudaFuncSetAttribute(mm_h<1>, cudaFuncAttributeMaxDynamicSharedMemorySize, SMEM_BYTES);
    cudaFuncSetAttribute(mm_h<2>, cudaFuncAttributeMaxDynamicSharedMemorySize, SMEM_BYTES);
    cudaFuncSetAttribute(mm_h<3>, cudaFuncAttributeMaxDynamicSharedMemorySize, SMEM_BYTES);
    cudaFuncSetAttribute(mm_h<4>, cudaFuncAttributeMaxDynamicSharedMemorySize, SMEM_BYTES);
    cudaFuncSetAttribute(mm_h<5>, cudaFuncAttributeMaxDynamicSharedMemorySize, SMEM_BYTES);

    // prep: convert x and Wq, transpose Wv, rank-1 bias terms (+D' init), zero M
    round_xh<<<(int)(((size_t)BT * En / 4) / 256), 256>>>(x, xr);
    round_xh<<<(int)(((size_t)En * Hn / 4) / 256), 256>>>(Wq, wqh);
    transpose_h<<<dim3(Hn / 32, En / 32), dim3(32, 8)>>>(Wv, wtv, En, Hn);
    prep_w2<<<En + 1, 256>>>(Wq, bq, w2, cS);
    prep_t<<<BT / 8, 256>>>(x, w2, cS, tV, dI);
    cudaMemsetAsync(mf, 0, (size_t)En * En * sizeof(float));

    // M = Wq @ Wq^T  split-K x4 into fp32 partials (full-width grid), then round
    mm_h<5><<<dim3(En / 128, En / 128, 4), 256, SMEM_BYTES>>>(
        wqh, wqh, nullptr, mf, nullptr, Hn / 4, Hn, Hn, En,
        (long long)(Hn / 4), (long long)(Hn / 4), 0);
    round_xh<<<(int)(((size_t)En * En / 4) / 256), 256>>>(mf, Mh);
    // y = x @ M                     [B*T, En] fp16  (M symmetric -> NT ok)
    mm_h<4><<<dim3(En / 128, BT / 128, 1), 256, SMEM_BYTES>>>(
        xr, Mh, nullptr, y, nullptr, En, En, En, En, 0, 0, 0);
    // E' = alpha*exp((y@x^T + t1' + 1t')*s), lower-tri blocks, fused col sums -> D'
    mm_h<2><<<dim3(NBK * (NBK + 1) / 2, 1, Bn), 256, SMEM_BYTES>>>(
        y, xr, tV, e, dI, En, En, En, Tn,
        (long long)Tn * En, (long long)Tn * En, (long long)Tn * Tn);
    // vt2 = BETA*(x @ Wv + bv)^T / D'    [H, B*T] fp16, scaling fused in epilogue
    mm_h<1><<<dim3(BT / 128, Hn / 128, 1), 256, SMEM_BYTES>>>(
        wtv, xr, bv, vt, dI, En, En, En, BT, 0, 0, 0);
    // alpha-scaled block-suffix sums of vt2
    suffix_v<<<dim3(Hn, Bn), 128>>>(vt, suf);
    // out = E'_tri @ vt2 / BETA + Suf[by+1]   per batch, heavy blocks first
    mm_h<3><<<dim3(Hn / 128, Tn / 128, Bn), 256, SMEM_BYTES>>>(
        e, vt, suf, out, nullptr, Tn, Tn, BT, Hn,
        (long long)Tn * Tn, (long long)Tn, (long long)Tn * Hn);
}